// round 9
// baseline (speedup 1.0000x reference)
#include <cuda_runtime.h>
#include <cuda_fp16.h>
#include <math.h>

#define EN   262144
#define NN   65536
#define RTT  8000
#define HH   64
#define BQn  40
#define RRn  200
#define SLOPE 0.22916666666666666f

typedef unsigned long long ull;

// ---------------- device scratch (no allocs allowed) ----------------
__device__ float  g_node[NN*HH], g_nacc[NN*HH];
__device__ __half g_projAh[NN*HH], g_projBh[NN*HH];
__device__ __half g_prh[RTT*HH], g_pqh[RTT*HH], g_pq2h[RTT*HH];
__device__ float  g_rel[RTT*HH], g_racc[RTT*HH];
__device__ float  g_finals[3*RTT*HH], g_fin[RTT*HH];
__device__ float  g_Ar[RTT], g_Aq[RTT], g_Br[RTT], g_Bq[RTT];
__device__ float  g_asum[NN], g_bsum[RTT], g_dinv2[NN];
__device__ float  g_aes[EN], g_bes[EN];
__device__ float  g_loop[BQn*HH];
__device__ int    g_qrows[BQn];
__device__ int    g_cnt_n[NN], g_off_n[NN+1], g_cur_n[NN];
__device__ int    g_cnt_t[RTT], g_off_t[RTT+1], g_cur_t[RTT];
__device__ int    g_aux[128];
__device__ int2   g_recN[EN];   // (col | et<<16, eq) grouped by row
__device__ int2   g_recT[EN];   // (col | row<<16, eq) grouped by edge_type

__device__ __forceinline__ float actf(float x){ return x >= 0.f ? x : x*SLOPE; }

__device__ __forceinline__ ull pk2(float x, float y){
    ull r; asm("mov.b64 %0, {%1, %2};" : "=l"(r) : "f"(x), "f"(y)); return r;
}
__device__ __forceinline__ void upk2(ull v, float& x, float& y){
    asm("mov.b64 {%0, %1}, %2;" : "=f"(x), "=f"(y) : "l"(v));
}
__device__ __forceinline__ void ffma2(ull& d, ull a, ull b){
    asm("fma.rn.f32x2 %0, %1, %2, %0;" : "+l"(d) : "l"(a), "l"(b));
}

// ---------------- init + hist (fused; relies on tail-zeroing from prior call) ----------------
#define INIT_NODE_BLK (NN*HH/256)          // 16384
#define INIT_REL_BLK  (BQn*HH/256)         // 10
#define INIT_HIST_BLK (EN/256)             // 1024
__global__ void k_inithist(const int* __restrict__ labels, const float* __restrict__ pos_emb,
                           const int* __restrict__ hp, const int* __restrict__ tp,
                           const int* __restrict__ qrel, const float* __restrict__ srel,
                           const float* __restrict__ lemb,
                           const int* __restrict__ row, const int* __restrict__ et){
    int t = threadIdx.x;
    int b = blockIdx.x;
    if (b < INIT_NODE_BLK){
        __shared__ int shp[BQn], stp[BQn], ssrc[4];
        if (t < BQn) shp[t] = hp[t];
        else if (t < 2*BQn) stp[t-BQn] = tp[t-BQn];
        __syncthreads();
        if (t < 4){
            int n = b*4 + t;
            int s = -1;
            #pragma unroll
            for (int q = 0; q < BQn; q++) if (shp[q] == n) s = 0;
            #pragma unroll
            for (int q = 0; q < BQn; q++) if (stp[q] == n) s = 1;  // t overrides h
            ssrc[t] = s;
        }
        __syncthreads();
        int idx = b*256 + t;
        int n = idx >> 6, h = idx & 63;
        int src = ssrc[(idx >> 6) & 3];
        float v;
        if (src < 0){
            int pp = labels[2*n]*4 + labels[2*n+1];
            v = pos_emb[pp*HH + h];
        } else {
            v = pos_emb[src*HH + h];
        }
        g_node[idx] = v;
    } else if (b < INIT_NODE_BLK + INIT_REL_BLK){
        int idx = (b - INIT_NODE_BLK)*256 + t;
        int q = idx >> 6, h = idx & 63;
        int qrow = qrel[q] + q*RRn;
        if (h == 0) g_qrows[q] = qrow;
        g_rel[qrow*HH + h] = srel[h];   // rest of g_rel zeroed by prior call's k_mean tail
        g_loop[idx] = lemb[h];
    } else {
        int e = (b - INIT_NODE_BLK - INIT_REL_BLK)*256 + t;
        atomicAdd(&g_cnt_n[row[e]], 1);
        atomicAdd(&g_cnt_t[et[e]], 1);
    }
}

// ---------------- CSR scans ----------------
__device__ __forceinline__ void scan1_body(const int* cnt, int* off, int* aux, int n, int blk){
    __shared__ int sh[1024];
    int t = threadIdx.x, i = blk*1024 + t;
    int v = (i < n) ? cnt[i] : 0;
    sh[t] = v; __syncthreads();
    for (int d = 1; d < 1024; d <<= 1){
        int u = (t >= d) ? sh[t-d] : 0;
        __syncthreads();
        sh[t] += u;
        __syncthreads();
    }
    if (i < n) off[i] = sh[t] - v;
    if (t == 1023) aux[blk] = sh[t];
}

__global__ void k_scan1(){
    if (blockIdx.x < 64) scan1_body(g_cnt_n, g_off_n, g_aux, NN, blockIdx.x);
    else                 scan1_body(g_cnt_t, g_off_t, g_aux + 64, RTT, blockIdx.x - 64);
}

// scan3 computes its own aux prefix in-block (scan2 eliminated)
__device__ __forceinline__ int aux_prefix(const int* aux, int upto){
    __shared__ int sa[64];
    int t = threadIdx.x;
    if (t < 64) sa[t] = (t < upto) ? aux[t] : 0;
    __syncthreads();
    if (t < 32) sa[t] += sa[t+32];
    __syncthreads();
    int base = 0;
    if (t < 32){
        int v = sa[t];
        #pragma unroll
        for (int o=16;o;o>>=1) v += __shfl_down_sync(0xffffffffu, v, o);
        if (t == 0) sa[0] = v;
    }
    __syncthreads();
    base = sa[0];
    __syncthreads();
    return base;
}

__global__ void k_scan3(){
    int t = threadIdx.x;
    if (blockIdx.x < 64){
        int blk = blockIdx.x;
        int base = aux_prefix(g_aux, blk);
        int i = blk*1024 + t;
        int o = g_off_n[i] + base;
        g_off_n[i] = o; g_cur_n[i] = o;
        int c = g_cnt_n[i];
        g_dinv2[i] = c > 0 ? 1.f/(float)c : 0.f;
        if (i == 0) g_off_n[NN] = EN;
    } else {
        int b2 = blockIdx.x - 64;
        int base = aux_prefix(g_aux + 64, b2);
        int i = b2*1024 + t;
        if (i < RTT){
            int o = g_off_t[i] + base;
            g_off_t[i] = o; g_cur_t[i] = o;
        }
        if (i == 0) g_off_t[RTT] = EN;
    }
}

// ---------------- per-relation attention scalars (layer 0) ----------------
__device__ __forceinline__ void relscal_body(int b2, const float* __restrict__ Wa,
        const float* __restrict__ Wb, const float* __restrict__ ba, const float* __restrict__ bb){
    int w = b2*8 + (threadIdx.x >> 5);
    int lane = threadIdx.x & 31;
    if (w >= RTT) return;
    float2 v = *(const float2*)(g_rel + (size_t)w*HH + 2*lane);
    float a0 = actf(v.x), a1 = actf(v.y);
    float2 wa1 = *(const float2*)(Wa + 2*lane);
    float2 wa2 = *(const float2*)(Wa + 64 + 2*lane);
    float2 wb1 = *(const float2*)(Wb + 2*lane);
    float2 wb2 = *(const float2*)(Wb + 64 + 2*lane);
    float sar = a0*wa1.x + a1*wa1.y;
    float saq = a0*wa2.x + a1*wa2.y;
    float sbr = v.x*wb1.x + v.y*wb1.y;
    float sbq = v.x*wb2.x + v.y*wb2.y;
    #pragma unroll
    for (int o=16;o;o>>=1){
        sar += __shfl_xor_sync(0xffffffffu,sar,o);
        saq += __shfl_xor_sync(0xffffffffu,saq,o);
        sbr += __shfl_xor_sync(0xffffffffu,sbr,o);
        sbq += __shfl_xor_sync(0xffffffffu,sbq,o);
    }
    if (lane == 0){ g_Ar[w]=sar+ba[0]; g_Aq[w]=saq; g_Br[w]=sbr+bb[0]; g_Bq[w]=sbq; }
}

// ---------------- core proj body ----------------
template<int TWO, int DOLN, int DOSCAL>
__device__ __forceinline__ void proj_body(
        int blk, const float* __restrict__ in, int nchunk, size_t cstride,
        const float* __restrict__ W, int wstride, int co1, int co2,
        void* __restrict__ out1, void* __restrict__ out2,
        const float* __restrict__ bias, const float* __restrict__ resid,
        float* __restrict__ outB,
        const float* __restrict__ Wa2, const float* __restrict__ Wb2,
        const float* __restrict__ ba2, const float* __restrict__ bb2)
{
    __shared__ float In[64][68];
    __shared__ float Wt[TWO+1][32][66];
    const int t = threadIdx.x;
    const int op = t & 31, rg = t >> 5;
    const size_t rowbase = (size_t)blk * 64;

    ull A0[4], B0[4], A1[4], B1[4];
    {
        ull z = pk2(0.f, 0.f);
        #pragma unroll
        for (int j=0;j<4;j++){ A0[j]=z; B0[j]=z; A1[j]=z; B1[j]=z; }
    }

    for (int c = 0; c < nchunk; c++){
        #pragma unroll 1
        for (int h = 0; h < 2; h++){
            __syncthreads();
            if (h == 0){
                const float* inc = in + (size_t)c*cstride + rowbase*HH;
                for (int idx = t; idx < 1024; idx += 256){
                    int r = idx & 63, kq = idx >> 6;
                    float4 v = *(const float4*)(inc + (size_t)r*HH + 4*kq);
                    In[4*kq+0][r]=v.x; In[4*kq+1][r]=v.y;
                    In[4*kq+2][r]=v.z; In[4*kq+3][r]=v.w;
                }
            }
            {
                int cob = c*64 + h*32;
                for (int idx = t; idx < 2048; idx += 256){
                    int o = idx >> 5, k = idx & 31;
                    Wt[0][k][o] = W[o*wstride + co1 + cob + k];
                    if (TWO) Wt[TWO][k][o] = W[o*wstride + co2 + cob + k];
                }
            }
            __syncthreads();
            #pragma unroll 8
            for (int k = 0; k < 32; k++){
                ulonglong2 v01 = *(const ulonglong2*)&In[h*32+k][rg*8];
                ulonglong2 v23 = *(const ulonglong2*)&In[h*32+k][rg*8+4];
                float2 w0 = *(const float2*)&Wt[0][k][2*op];
                ull wa = pk2(w0.x, w0.x), wb = pk2(w0.y, w0.y);
                ffma2(A0[0], v01.x, wa); ffma2(A0[1], v01.y, wa);
                ffma2(A0[2], v23.x, wa); ffma2(A0[3], v23.y, wa);
                ffma2(B0[0], v01.x, wb); ffma2(B0[1], v01.y, wb);
                ffma2(B0[2], v23.x, wb); ffma2(B0[3], v23.y, wb);
                if (TWO){
                    float2 w1 = *(const float2*)&Wt[TWO][k][2*op];
                    ull wc = pk2(w1.x, w1.x), wd = pk2(w1.y, w1.y);
                    ffma2(A1[0], v01.x, wc); ffma2(A1[1], v01.y, wc);
                    ffma2(A1[2], v23.x, wc); ffma2(A1[3], v23.y, wc);
                    ffma2(B1[0], v01.x, wd); ffma2(B1[1], v01.y, wd);
                    ffma2(B1[2], v23.x, wd); ffma2(B1[3], v23.y, wd);
                }
            }
        }
    }

    if (!DOLN){
        __half2* o1h = (__half2*)out1;
        __half2* o2h = (__half2*)out2;
        #pragma unroll
        for (int j = 0; j < 4; j++){
            size_t r0 = rowbase + rg*8 + 2*j;
            float a0,a1,b0,b1;
            upk2(A0[j], a0, a1); upk2(B0[j], b0, b1);
            o1h[r0*32 + op]     = __float22half2_rn(make_float2(a0, b0));
            o1h[(r0+1)*32 + op] = __float22half2_rn(make_float2(a1, b1));
            if (TWO){
                upk2(A1[j], a0, a1); upk2(B1[j], b0, b1);
                o2h[r0*32 + op]     = __float22half2_rn(make_float2(a0, b0));
                o2h[(r0+1)*32 + op] = __float22half2_rn(make_float2(a1, b1));
            }
        }
    } else {
        float* o1f = (float*)out1;
        float2 bv = *(const float2*)(bias + 2*op);
        float2 wa1, wav2, wb1, wbv2;
        bool doscal = DOSCAL && (Wa2 != 0);
        if (DOSCAL && doscal){
            wa1  = *(const float2*)(Wa2 + 2*op);
            wav2 = *(const float2*)(Wa2 + 64 + 2*op);
            wb1  = *(const float2*)(Wb2 + 2*op);
            wbv2 = *(const float2*)(Wb2 + 64 + 2*op);
        }
        #pragma unroll
        for (int j = 0; j < 4; j++){
            size_t r0 = rowbase + rg*8 + 2*j;
            float a0,a1,b0,b1;
            upk2(A0[j], a0, a1); upk2(B0[j], b0, b1);
            float y00 = actf(a0 + bv.x), y01 = actf(b0 + bv.y);
            float y10 = actf(a1 + bv.x), y11 = actf(b1 + bv.y);
            if (resid){
                float2 rv0 = *(const float2*)(resid + r0*HH + 2*op);
                float2 rv1 = *(const float2*)(resid + (r0+1)*HH + 2*op);
                y00 += rv0.x; y01 += rv0.y; y10 += rv1.x; y11 += rv1.y;
            }
            float s0 = y00+y01, q0 = y00*y00+y01*y01;
            float s1 = y10+y11, q1 = y10*y10+y11*y11;
            #pragma unroll
            for (int o=16;o;o>>=1){
                s0 += __shfl_xor_sync(0xffffffffu,s0,o);
                q0 += __shfl_xor_sync(0xffffffffu,q0,o);
                s1 += __shfl_xor_sync(0xffffffffu,s1,o);
                q1 += __shfl_xor_sync(0xffffffffu,q1,o);
            }
            float m0 = s0*(1.f/64.f), m1 = s1*(1.f/64.f);
            float i0 = rsqrtf(q0*(1.f/64.f) - m0*m0 + 1e-5f);
            float i1 = rsqrtf(q1*(1.f/64.f) - m1*m1 + 1e-5f);
            float2 w0 = make_float2((y00-m0)*i0, (y01-m0)*i0);
            float2 w1 = make_float2((y10-m1)*i1, (y11-m1)*i1);
            *(float2*)(o1f + r0*HH + 2*op)     = w0;
            *(float2*)(o1f + (r0+1)*HH + 2*op) = w1;
            if (outB){
                *(float2*)(outB + r0*HH + 2*op)     = w0;
                *(float2*)(outB + (r0+1)*HH + 2*op) = w1;
            }
            if (DOSCAL && doscal){
                float pa0 = actf(w0.x)*wa1.x + actf(w0.y)*wa1.y;
                float pq0 = actf(w0.x)*wav2.x + actf(w0.y)*wav2.y;
                float pb0 = w0.x*wb1.x + w0.y*wb1.y;
                float pc0 = w0.x*wbv2.x + w0.y*wbv2.y;
                float pa1 = actf(w1.x)*wa1.x + actf(w1.y)*wa1.y;
                float pq1 = actf(w1.x)*wav2.x + actf(w1.y)*wav2.y;
                float pb1 = w1.x*wb1.x + w1.y*wb1.y;
                float pc1 = w1.x*wbv2.x + w1.y*wbv2.y;
                #pragma unroll
                for (int o=16;o;o>>=1){
                    pa0 += __shfl_xor_sync(0xffffffffu,pa0,o);
                    pq0 += __shfl_xor_sync(0xffffffffu,pq0,o);
                    pb0 += __shfl_xor_sync(0xffffffffu,pb0,o);
                    pc0 += __shfl_xor_sync(0xffffffffu,pc0,o);
                    pa1 += __shfl_xor_sync(0xffffffffu,pa1,o);
                    pq1 += __shfl_xor_sync(0xffffffffu,pq1,o);
                    pb1 += __shfl_xor_sync(0xffffffffu,pb1,o);
                    pc1 += __shfl_xor_sync(0xffffffffu,pc1,o);
                }
                if (op == 0){
                    g_Ar[r0]   = pa0 + ba2[0]; g_Aq[r0]   = pq0;
                    g_Br[r0]   = pb0 + bb2[0]; g_Bq[r0]   = pc0;
                    g_Ar[r0+1] = pa1 + ba2[0]; g_Aq[r0+1] = pq1;
                    g_Br[r0+1] = pb1 + bb2[0]; g_Bq[r0+1] = pc1;
                }
            }
        }
    }
}

// ---------------- scatter (int2-packed) | relscal L0 | zero cnt | layer-0 projections ----------------
__global__ __launch_bounds__(256, 3) void k_scatter(const int* __restrict__ col,
        const int* __restrict__ row, const int* __restrict__ et, const int* __restrict__ eq,
        const float* __restrict__ Wa0, const float* __restrict__ Wb0,
        const float* __restrict__ ba0, const float* __restrict__ bb0,
        const float* __restrict__ Wmsg0, const float* __restrict__ Wht0){
    int b = blockIdx.x;
    if (b < 1024){
        int e = b*blockDim.x + threadIdx.x;
        int c = col[e], r = row[e], t = et[e], q = eq[e];
        int p  = atomicAdd(&g_cur_n[r], 1);
        g_recN[p] = make_int2(c | (t << 16), q);
        int p2 = atomicAdd(&g_cur_t[t], 1);
        g_recT[p2] = make_int2(c | (r << 16), q);
    } else if (b < 2024){
        relscal_body(b - 1024, Wa0, Wb0, ba0, bb0);
    } else if (b < 2280){
        g_cnt_n[(b-2024)*256 + threadIdx.x] = 0;
    } else if (b < 2312){
        int i = (b-2280)*256 + threadIdx.x;
        if (i < RTT) g_cnt_t[i] = 0;
    } else if (b < 2437){
        proj_body<1,0,0>(b-2312, g_rel, 1, 0, Wmsg0, 192, 64, 128, g_prh, g_pqh, 0, 0, 0, 0,0,0,0);
    } else if (b < 2562){
        proj_body<0,0,0>(b-2437, g_rel, 1, 0, Wht0, 192, 128, 0, g_pq2h, 0, 0, 0, 0, 0,0,0,0);
    } else {
        proj_body<0,0,0>(b-2562, g_node, 1, 0, Wmsg0, 192, 0, 0, g_projAh, 0, 0, 0, 0, 0,0,0,0);
    }
}

// ---------------- attention segment sums (body) ----------------
__device__ __forceinline__ void absum_body(int b2){
    if (b2 < 256){
        int n = b2*256 + threadIdx.x;
        int b = g_off_n[n], e = g_off_n[n+1];
        float s = 0.f;
        for (int j = b; j < e; j++){
            int2 rc = g_recN[j];
            float a = __expf(g_Ar[((unsigned)rc.x) >> 16] + g_Aq[rc.y]);
            g_aes[j] = a; s += a;
        }
        g_asum[n] = s;
    } else {
        int w = (b2 - 256)*8 + (threadIdx.x >> 5);
        int lane = threadIdx.x & 31;
        if (w >= RTT) return;
        int b = g_off_t[w], e = g_off_t[w+1];
        float br = g_Br[w];
        float s = 0.f;
        for (int j = b + lane; j < e; j += 32){
            float bv = __expf(br + g_Bq[g_recT[j].y]);
            g_bes[j] = bv; s += bv;
        }
        #pragma unroll
        for (int o=16;o;o>>=1) s += __shfl_xor_sync(0xffffffffu,s,o);
        if (lane == 0) g_bsum[w] = s;
    }
}

// layer-0 absum (projections already done in scatter grid)
__global__ void k_absum0(){
    absum_body(blockIdx.x);
}

// ---------------- loop update: one warp per query ----------------
__device__ __forceinline__ void loop_warp(int q, const float* __restrict__ Wl,
                                          const float* __restrict__ bl){
    int lane = threadIdx.x & 31;
    int qrow = g_qrows[q];
    float2 lv = *(const float2*)(g_loop + q*HH + 2*lane);
    float s0 = bl[2*lane], s1 = bl[2*lane+1];
    const float* lrow = g_loop + q*HH;
    const float* rrow = g_rel + (size_t)qrow*HH;
    const float* w0p = Wl + (size_t)(2*lane)*128;
    const float* w1p = w0p + 128;
    #pragma unroll 8
    for (int k = 0; k < 64; k++){
        float c = lrow[k];
        s0 = fmaf(c, w0p[k], s0); s1 = fmaf(c, w1p[k], s1);
    }
    #pragma unroll 8
    for (int k = 0; k < 64; k++){
        float c = rrow[k];
        s0 = fmaf(c, w0p[64+k], s0); s1 = fmaf(c, w1p[64+k], s1);
    }
    float y0 = lv.x + actf(s0), y1 = lv.y + actf(s1);
    float ss = y0+y1, sq = y0*y0+y1*y1;
    #pragma unroll
    for (int o=16;o;o>>=1){
        ss += __shfl_xor_sync(0xffffffffu,ss,o);
        sq += __shfl_xor_sync(0xffffffffu,sq,o);
    }
    float m = ss*(1.f/64.f);
    float inv = rsqrtf(sq*(1.f/64.f) - m*m + 1e-5f);
    *(float2*)(g_loop + q*HH + 2*lane) = make_float2((y0-m)*inv, (y1-m)*inv);
}

// ---------------- stage kernels ----------------
// stage1 (layers >=1): Pr+Pq (dual) | Pq2 | Ph (node) | absum | loop(prev)
__global__ __launch_bounds__(256, 3) void k_stage1(const float* __restrict__ Wmsg,
        const float* __restrict__ Wht,
        const float* __restrict__ Wl_prev, const float* __restrict__ bl_prev){
    int b = blockIdx.x;
    if (b < 125)
        proj_body<1,0,0>(b, g_rel, 1, 0, Wmsg, 192, 64, 128, g_prh, g_pqh, 0, 0, 0, 0,0,0,0);
    else if (b < 250)
        proj_body<0,0,0>(b-125, g_rel, 1, 0, Wht, 192, 128, 0, g_pq2h, 0, 0, 0, 0, 0,0,0,0);
    else if (b < 1274)
        proj_body<0,0,0>(b-250, g_node, 1, 0, Wmsg, 192, 0, 0, g_projAh, 0, 0, 0, 0, 0,0,0,0);
    else if (b < 2530)
        absum_body(b-1274);
    else {
        if (threadIdx.x < 32) loop_warp(b-2530, Wl_prev, bl_prev);
    }
}

// stage4: Ph2+Pt2 (node dual)
__global__ __launch_bounds__(256, 3) void k_stage4(const float* __restrict__ Wht){
    proj_body<1,0,0>(blockIdx.x, g_node, 1, 0, Wht, 192, 0, 64, g_projAh, g_projBh, 0, 0, 0, 0,0,0,0);
}

// stage3: node = LN(act(nacc @ We^T + be))
__global__ __launch_bounds__(256, 3) void k_stage3(const float* __restrict__ We,
        const float* __restrict__ be){
    proj_body<0,1,0>(blockIdx.x, g_nacc, 1, 0, We, 64, 0, 0, g_node, 0, be, 0, 0, 0,0,0,0);
}

// stage6: rel = LN(act(racc @ Wr^T + br) + rel); finals[i]; + next-layer relscal
__global__ __launch_bounds__(256, 3) void k_stage6(const float* __restrict__ Wr,
        const float* __restrict__ br, float* __restrict__ finals_i,
        const float* __restrict__ Wa2, const float* __restrict__ Wb2,
        const float* __restrict__ ba2, const float* __restrict__ bb2){
    proj_body<0,1,1>(blockIdx.x, g_racc, 1, 0, Wr, 64, 0, 0, g_rel, 0, br, g_rel, finals_i,
                     Wa2, Wb2, ba2, bb2);
}

// final: fin = LN(act(concat(finals) @ Wf^T + bf)) | loop(layer 2)
__global__ __launch_bounds__(256, 3) void k_final(const float* __restrict__ Wf,
        const float* __restrict__ bf, const float* __restrict__ Wl2,
        const float* __restrict__ bl2){
    int b = blockIdx.x;
    if (b < 125)
        proj_body<0,1,0>(b, g_finals, 3, (size_t)RTT*HH, Wf, 192, 0, 0, g_fin, 0, bf, 0, 0, 0,0,0,0);
    else {
        if (threadIdx.x < 32) loop_warp(b-125, Wl2, bl2);
    }
}

// ---------------- edge message aggregation: half-warp per edge stream (2-way) ----------------
__global__ void k_msg_agg(const int* __restrict__ row, const float* __restrict__ bmsg){
    int w = (blockIdx.x*blockDim.x + threadIdx.x) >> 5;
    int lane = threadIdx.x & 31;
    if (w >= NN) return;
    int half = lane >> 4, hl = lane & 15;     // dims 4hl..4hl+3
    int b = g_off_n[w], e = g_off_n[w+1];
    float denom = g_asum[row[w]] + 1e-10f;    // faithful a_sum[row[row_e]]
    float sc0 = g_dinv2[w] / denom;
    float4 bm = *(const float4*)(bmsg + 4*hl);
    const __half2* phA = (const __half2*)g_projAh;
    const __half2* phR = (const __half2*)g_prh;
    const __half2* phQ = (const __half2*)g_pqh;
    float4 acc = make_float4(0.f,0.f,0.f,0.f);
    for (int j = b + half; j < e; j += 2){
        int2 rc = g_recN[j];
        int cl = rc.x & 0xFFFF;
        int tt = ((unsigned)rc.x) >> 16;
        float coef = g_aes[j] * sc0 * g_dinv2[cl];
        float2 pa0 = __half22float2(phA[(size_t)cl*32 + 2*hl]);
        float2 pa1 = __half22float2(phA[(size_t)cl*32 + 2*hl + 1]);
        float2 pr0 = __half22float2(phR[(size_t)tt*32 + 2*hl]);
        float2 pr1 = __half22float2(phR[(size_t)tt*32 + 2*hl + 1]);
        float2 pq0 = __half22float2(phQ[(size_t)rc.y*32 + 2*hl]);
        float2 pq1 = __half22float2(phQ[(size_t)rc.y*32 + 2*hl + 1]);
        acc.x += coef*actf(pa0.x + pr0.x + pq0.x + bm.x);
        acc.y += coef*actf(pa0.y + pr0.y + pq0.y + bm.y);
        acc.z += coef*actf(pa1.x + pr1.x + pq1.x + bm.z);
        acc.w += coef*actf(pa1.y + pr1.y + pq1.y + bm.w);
    }
    acc.x += __shfl_down_sync(0xffffffffu, acc.x, 16);
    acc.y += __shfl_down_sync(0xffffffffu, acc.y, 16);
    acc.z += __shfl_down_sync(0xffffffffu, acc.z, 16);
    acc.w += __shfl_down_sync(0xffffffffu, acc.w, 16);
    if (half == 0) *(float4*)(g_nacc + (size_t)w*HH + 4*hl) = acc;
}

// ---------------- ht2r aggregation: quarter-warp per edge stream (4-way) ----------------
__global__ void k_ht2r_agg(const int* __restrict__ et, const float* __restrict__ bht){
    int w = (blockIdx.x*blockDim.x + threadIdx.x) >> 5;
    int lane = threadIdx.x & 31;
    if (w >= RTT) return;
    int qd = lane >> 3, ql = lane & 7;   // dims 8ql..8ql+7
    int b = g_off_t[w], e = g_off_t[w+1];
    float inv_denom = 1.f / (g_bsum[et[w]] + 1e-10f);  // faithful b_sum[et[et_e]]
    float4 bm0 = *(const float4*)(bht + 8*ql);
    float4 bm1 = *(const float4*)(bht + 8*ql + 4);
    const __half2* phA = (const __half2*)g_projAh;
    const __half2* phB = (const __half2*)g_projBh;
    const __half2* phQ = (const __half2*)g_pq2h;
    float acc[8];
    #pragma unroll
    for (int x=0;x<8;x++) acc[x] = 0.f;
    for (int j = b + qd; j < e; j += 4){
        int2 rc = g_recT[j];
        int cl = rc.x & 0xFFFF;
        unsigned rw = ((unsigned)rc.x) >> 16;
        float coef = g_bes[j] * inv_denom;
        float2 pa[4], pt[4], pq[4];
        #pragma unroll
        for (int x=0;x<4;x++){
            pa[x] = __half22float2(phA[(size_t)cl*32 + 4*ql + x]);
            pt[x] = __half22float2(phB[(size_t)rw*32 + 4*ql + x]);
            pq[x] = __half22float2(phQ[(size_t)rc.y*32 + 4*ql + x]);
        }
        acc[0] += coef*actf(pa[0].x + pt[0].x + pq[0].x + bm0.x);
        acc[1] += coef*actf(pa[0].y + pt[0].y + pq[0].y + bm0.y);
        acc[2] += coef*actf(pa[1].x + pt[1].x + pq[1].x + bm0.z);
        acc[3] += coef*actf(pa[1].y + pt[1].y + pq[1].y + bm0.w);
        acc[4] += coef*actf(pa[2].x + pt[2].x + pq[2].x + bm1.x);
        acc[5] += coef*actf(pa[2].y + pt[2].y + pq[2].y + bm1.y);
        acc[6] += coef*actf(pa[3].x + pt[3].x + pq[3].x + bm1.z);
        acc[7] += coef*actf(pa[3].y + pt[3].y + pq[3].y + bm1.w);
    }
    #pragma unroll
    for (int x=0;x<8;x++){
        acc[x] += __shfl_down_sync(0xffffffffu, acc[x], 16);
        acc[x] += __shfl_down_sync(0xffffffffu, acc[x], 8);
    }
    if (qd == 0){
        *(float4*)(g_racc + (size_t)w*HH + 8*ql)     = make_float4(acc[0],acc[1],acc[2],acc[3]);
        *(float4*)(g_racc + (size_t)w*HH + 8*ql + 4) = make_float4(acc[4],acc[5],acc[6],acc[7]);
    }
}

// ---------------- output means | zero rel for next call ----------------
__global__ void k_mean(float* __restrict__ out){
    int b = blockIdx.x;
    if (b < 402){
        int idx = b*256 + threadIdx.x;
        if (idx >= 8*201*64) return;
        int h = idx & 63;
        int rb = idx >> 6;
        int r = rb % 201;
        int bq = rb / 201;
        float s = 0.f;
        if (r < 200){
            #pragma unroll
            for (int s5=0;s5<5;s5++) s += g_fin[(bq*1000 + s5*200 + r)*HH + h];
        } else {
            #pragma unroll
            for (int s5=0;s5<5;s5++) s += g_loop[(bq*5 + s5)*HH + h];
        }
        out[idx] = s * 0.2f;
    } else {
        g_rel[(b-402)*256 + threadIdx.x] = 0.f;   // RTT*HH = 512000 = 2000 blocks
    }
}

// ---------------- host ----------------
struct Ptrs {
    const int *ei,*et,*eq,*hp,*tp,*qr,*lab;
    const float *pos,*srel,*lemb,*Wmsg,*bmsg,*Wht,*bht,*Wa,*ba,*Wb,*bb,*Wl,*bl,*We,*be,*Wr,*br,*Wf,*bf;
};

static void resolve(void* const* d, const int* sz, int n, Ptrs& p){
    int gi, wi;
    if (sz[0] == 2*EN){
        gi = 0;
        wi = (n > 10 && sz[7] == 1 && sz[8] == 1 && sz[9] == 1) ? 10 : 7;
    } else {
        wi = 0; gi = 19;
    }
    p.ei  = (const int*)d[gi+0]; p.et = (const int*)d[gi+1]; p.eq = (const int*)d[gi+2];
    p.hp  = (const int*)d[gi+3]; p.tp = (const int*)d[gi+4]; p.qr = (const int*)d[gi+5];
    p.lab = (const int*)d[gi+6];
    p.pos  = (const float*)d[wi+0];  p.srel = (const float*)d[wi+1];  p.lemb = (const float*)d[wi+2];
    p.Wmsg = (const float*)d[wi+3];  p.bmsg = (const float*)d[wi+4];
    p.Wht  = (const float*)d[wi+5];  p.bht  = (const float*)d[wi+6];
    p.Wa   = (const float*)d[wi+7];  p.ba   = (const float*)d[wi+8];
    p.Wb   = (const float*)d[wi+9];  p.bb   = (const float*)d[wi+10];
    p.Wl   = (const float*)d[wi+11]; p.bl   = (const float*)d[wi+12];
    p.We   = (const float*)d[wi+13]; p.be   = (const float*)d[wi+14];
    p.Wr   = (const float*)d[wi+15]; p.br   = (const float*)d[wi+16];
    p.Wf   = (const float*)d[wi+17]; p.bf   = (const float*)d[wi+18];
}

extern "C" void kernel_launch(void* const* d_in, const int* in_sizes, int n_in,
                              void* d_out, int out_size){
    Ptrs p; resolve(d_in, in_sizes, n_in, p);
    const int* col = p.ei;
    const int* row = p.ei + EN;

    float* s_finals;
    cudaGetSymbolAddress((void**)&s_finals, g_finals);

    // ---- init + CSR build (cnt/rel pre-zeroed by prior call's tails / module load) ----
    k_inithist<<<INIT_NODE_BLK + INIT_REL_BLK + INIT_HIST_BLK, 256>>>(
        p.lab, p.pos, p.hp, p.tp, p.qr, p.srel, p.lemb, row, p.et);
    k_scan1<<<72,1024>>>();
    k_scan3<<<72,1024>>>();
    // scatter + layer-0 relscal + cnt zero + layer-0 projections
    k_scatter<<<3586,256>>>(col, row, p.et, p.eq, p.Wa, p.Wb, p.ba, p.bb,
                            p.Wmsg, p.Wht);

    for (int i = 0; i < 3; i++){
        const float* Wmsg = p.Wmsg + i*HH*192;
        const float* bmsg = p.bmsg + i*HH;
        const float* Wht  = p.Wht  + i*HH*192;
        const float* bht  = p.bht  + i*HH;
        const float* Wa2 = (i < 2) ? (p.Wa + (i+1)*128) : (const float*)0;
        const float* Wb2 = (i < 2) ? (p.Wb + (i+1)*128) : (const float*)0;
        const float* ba2 = (i < 2) ? (p.ba + (i+1)) : (const float*)0;
        const float* bb2 = (i < 2) ? (p.bb + (i+1)) : (const float*)0;

        if (i == 0){
            k_absum0<<<1256,256>>>();
        } else {
            k_stage1<<<2570,256>>>(Wmsg, Wht, p.Wl + (i-1)*HH*128, p.bl + (i-1)*HH);
        }
        k_msg_agg<<<NN*32/256,256>>>(row, bmsg);
        k_stage3<<<1024,256>>>(p.We + i*HH*HH, p.be + i*HH);
        k_stage4<<<1024,256>>>(Wht);
        k_ht2r_agg<<<RTT*32/256,256>>>(p.et, bht);
        k_stage6<<<125,256>>>(p.Wr + i*HH*HH, p.br + i*HH, s_finals + i*RTT*HH,
                              Wa2, Wb2, ba2, bb2);
    }

    k_final<<<165,256>>>(p.Wf, p.bf, p.Wl + 2*HH*128, p.bl + 2*HH);
    k_mean<<<2402,256>>>((float*)d_out);
}

// round 10
// speedup vs baseline: 1.0008x; 1.0008x over previous
#include <cuda_runtime.h>
#include <cuda_fp16.h>
#include <math.h>

#define EN   262144
#define NN   65536
#define RTT  8000
#define HH   64
#define BQn  40
#define RRn  200
#define SLOPE 0.22916666666666666f

typedef unsigned long long ull;

// ---------------- device scratch (no allocs allowed) ----------------
__device__ float  g_node[NN*HH], g_nacc[NN*HH];
__device__ __half g_projAh[NN*HH], g_projBh[NN*HH];
__device__ __half g_prh[RTT*HH], g_pqh[RTT*HH], g_pq2h[RTT*HH];
__device__ float  g_rel[RTT*HH], g_racc[RTT*HH];
__device__ float  g_finals[3*RTT*HH], g_fin[RTT*HH];
__device__ float  g_Ar[RTT], g_Aq[RTT], g_Br[RTT], g_Bq[RTT];
__device__ float  g_asum[NN], g_bsum[RTT], g_dinv2[NN];
__device__ float  g_aes[EN], g_bes[EN];
__device__ float  g_loop[BQn*HH];
__device__ int    g_qrows[BQn];
__device__ int    g_cnt_n[NN], g_off_n[NN+1], g_cur_n[NN];
__device__ int    g_cnt_t[RTT], g_off_t[RTT+1], g_cur_t[RTT];
__device__ int    g_aux[128];
__device__ int2   g_recN[EN];   // (col | et<<16, eq) grouped by row
__device__ int2   g_recT[EN];   // (col | row<<16, eq) grouped by edge_type

__device__ __forceinline__ float actf(float x){ return x >= 0.f ? x : x*SLOPE; }

__device__ __forceinline__ ull pk2(float x, float y){
    ull r; asm("mov.b64 %0, {%1, %2};" : "=l"(r) : "f"(x), "f"(y)); return r;
}
__device__ __forceinline__ void upk2(ull v, float& x, float& y){
    asm("mov.b64 {%0, %1}, %2;" : "=f"(x), "=f"(y) : "l"(v));
}
__device__ __forceinline__ void ffma2(ull& d, ull a, ull b){
    asm("fma.rn.f32x2 %0, %1, %2, %0;" : "+l"(d) : "l"(a), "l"(b));
}

// ---------------- init + hist (fused; relies on tail-zeroing from prior call) ----------------
#define INIT_NODE_BLK (NN*HH/256)          // 16384
#define INIT_REL_BLK  (BQn*HH/256)         // 10
#define INIT_HIST_BLK (EN/256)             // 1024
__global__ void k_inithist(const int* __restrict__ labels, const float* __restrict__ pos_emb,
                           const int* __restrict__ hp, const int* __restrict__ tp,
                           const int* __restrict__ qrel, const float* __restrict__ srel,
                           const float* __restrict__ lemb,
                           const int* __restrict__ row, const int* __restrict__ et){
    int t = threadIdx.x;
    int b = blockIdx.x;
    if (b < INIT_NODE_BLK){
        __shared__ int shp[BQn], stp[BQn], ssrc[4];
        if (t < BQn) shp[t] = hp[t];
        else if (t < 2*BQn) stp[t-BQn] = tp[t-BQn];
        __syncthreads();
        if (t < 4){
            int n = b*4 + t;
            int s = -1;
            #pragma unroll
            for (int q = 0; q < BQn; q++) if (shp[q] == n) s = 0;
            #pragma unroll
            for (int q = 0; q < BQn; q++) if (stp[q] == n) s = 1;  // t overrides h
            ssrc[t] = s;
        }
        __syncthreads();
        int idx = b*256 + t;
        int n = idx >> 6, h = idx & 63;
        int src = ssrc[(idx >> 6) & 3];
        float v;
        if (src < 0){
            int pp = labels[2*n]*4 + labels[2*n+1];
            v = pos_emb[pp*HH + h];
        } else {
            v = pos_emb[src*HH + h];
        }
        g_node[idx] = v;
    } else if (b < INIT_NODE_BLK + INIT_REL_BLK){
        int idx = (b - INIT_NODE_BLK)*256 + t;
        int q = idx >> 6, h = idx & 63;
        int qrow = qrel[q] + q*RRn;
        if (h == 0) g_qrows[q] = qrow;
        g_rel[qrow*HH + h] = srel[h];   // rest of g_rel zeroed by prior call's k_mean tail
        g_loop[idx] = lemb[h];
    } else {
        int e = (b - INIT_NODE_BLK - INIT_REL_BLK)*256 + t;
        atomicAdd(&g_cnt_n[row[e]], 1);
        atomicAdd(&g_cnt_t[et[e]], 1);
    }
}

// ---------------- CSR scans ----------------
__device__ __forceinline__ void scan1_body(const int* cnt, int* off, int* aux, int n, int blk){
    __shared__ int sh[1024];
    int t = threadIdx.x, i = blk*1024 + t;
    int v = (i < n) ? cnt[i] : 0;
    sh[t] = v; __syncthreads();
    for (int d = 1; d < 1024; d <<= 1){
        int u = (t >= d) ? sh[t-d] : 0;
        __syncthreads();
        sh[t] += u;
        __syncthreads();
    }
    if (i < n) off[i] = sh[t] - v;
    if (t == 1023) aux[blk] = sh[t];
}

__global__ void k_scan1(){
    if (blockIdx.x < 64) scan1_body(g_cnt_n, g_off_n, g_aux, NN, blockIdx.x);
    else                 scan1_body(g_cnt_t, g_off_t, g_aux + 64, RTT, blockIdx.x - 64);
}

// scan3 computes its own aux prefix in-block (scan2 eliminated)
__device__ __forceinline__ int aux_prefix(const int* aux, int upto){
    __shared__ int sa[64];
    int t = threadIdx.x;
    if (t < 64) sa[t] = (t < upto) ? aux[t] : 0;
    __syncthreads();
    if (t < 32) sa[t] += sa[t+32];
    __syncthreads();
    int base = 0;
    if (t < 32){
        int v = sa[t];
        #pragma unroll
        for (int o=16;o;o>>=1) v += __shfl_down_sync(0xffffffffu, v, o);
        if (t == 0) sa[0] = v;
    }
    __syncthreads();
    base = sa[0];
    __syncthreads();
    return base;
}

__global__ void k_scan3(){
    int t = threadIdx.x;
    if (blockIdx.x < 64){
        int blk = blockIdx.x;
        int base = aux_prefix(g_aux, blk);
        int i = blk*1024 + t;
        int o = g_off_n[i] + base;
        g_off_n[i] = o; g_cur_n[i] = o;
        int c = g_cnt_n[i];
        g_dinv2[i] = c > 0 ? 1.f/(float)c : 0.f;
        if (i == 0) g_off_n[NN] = EN;
    } else {
        int b2 = blockIdx.x - 64;
        int base = aux_prefix(g_aux + 64, b2);
        int i = b2*1024 + t;
        if (i < RTT){
            int o = g_off_t[i] + base;
            g_off_t[i] = o; g_cur_t[i] = o;
        }
        if (i == 0) g_off_t[RTT] = EN;
    }
}

// ---------------- per-relation attention scalars (layer 0) ----------------
__device__ __forceinline__ void relscal_body(int b2, const float* __restrict__ Wa,
        const float* __restrict__ Wb, const float* __restrict__ ba, const float* __restrict__ bb){
    int w = b2*8 + (threadIdx.x >> 5);
    int lane = threadIdx.x & 31;
    if (w >= RTT) return;
    float2 v = *(const float2*)(g_rel + (size_t)w*HH + 2*lane);
    float a0 = actf(v.x), a1 = actf(v.y);
    float2 wa1 = *(const float2*)(Wa + 2*lane);
    float2 wa2 = *(const float2*)(Wa + 64 + 2*lane);
    float2 wb1 = *(const float2*)(Wb + 2*lane);
    float2 wb2 = *(const float2*)(Wb + 64 + 2*lane);
    float sar = a0*wa1.x + a1*wa1.y;
    float saq = a0*wa2.x + a1*wa2.y;
    float sbr = v.x*wb1.x + v.y*wb1.y;
    float sbq = v.x*wb2.x + v.y*wb2.y;
    #pragma unroll
    for (int o=16;o;o>>=1){
        sar += __shfl_xor_sync(0xffffffffu,sar,o);
        saq += __shfl_xor_sync(0xffffffffu,saq,o);
        sbr += __shfl_xor_sync(0xffffffffu,sbr,o);
        sbq += __shfl_xor_sync(0xffffffffu,sbq,o);
    }
    if (lane == 0){ g_Ar[w]=sar+ba[0]; g_Aq[w]=saq; g_Br[w]=sbr+bb[0]; g_Bq[w]=sbq; }
}

// ---------------- core proj body ----------------
template<int TWO, int DOLN, int DOSCAL>
__device__ __forceinline__ void proj_body(
        int blk, const float* __restrict__ in, int nchunk, size_t cstride,
        const float* __restrict__ W, int wstride, int co1, int co2,
        void* __restrict__ out1, void* __restrict__ out2,
        const float* __restrict__ bias, const float* __restrict__ resid,
        float* __restrict__ outB,
        const float* __restrict__ Wa2, const float* __restrict__ Wb2,
        const float* __restrict__ ba2, const float* __restrict__ bb2)
{
    __shared__ float In[64][68];
    __shared__ float Wt[TWO+1][32][66];
    const int t = threadIdx.x;
    const int op = t & 31, rg = t >> 5;
    const size_t rowbase = (size_t)blk * 64;

    ull A0[4], B0[4], A1[4], B1[4];
    {
        ull z = pk2(0.f, 0.f);
        #pragma unroll
        for (int j=0;j<4;j++){ A0[j]=z; B0[j]=z; A1[j]=z; B1[j]=z; }
    }

    for (int c = 0; c < nchunk; c++){
        #pragma unroll 1
        for (int h = 0; h < 2; h++){
            __syncthreads();
            if (h == 0){
                const float* inc = in + (size_t)c*cstride + rowbase*HH;
                for (int idx = t; idx < 1024; idx += 256){
                    int r = idx & 63, kq = idx >> 6;
                    float4 v = *(const float4*)(inc + (size_t)r*HH + 4*kq);
                    In[4*kq+0][r]=v.x; In[4*kq+1][r]=v.y;
                    In[4*kq+2][r]=v.z; In[4*kq+3][r]=v.w;
                }
            }
            {
                int cob = c*64 + h*32;
                for (int idx = t; idx < 2048; idx += 256){
                    int o = idx >> 5, k = idx & 31;
                    Wt[0][k][o] = W[o*wstride + co1 + cob + k];
                    if (TWO) Wt[TWO][k][o] = W[o*wstride + co2 + cob + k];
                }
            }
            __syncthreads();
            #pragma unroll 8
            for (int k = 0; k < 32; k++){
                ulonglong2 v01 = *(const ulonglong2*)&In[h*32+k][rg*8];
                ulonglong2 v23 = *(const ulonglong2*)&In[h*32+k][rg*8+4];
                float2 w0 = *(const float2*)&Wt[0][k][2*op];
                ull wa = pk2(w0.x, w0.x), wb = pk2(w0.y, w0.y);
                ffma2(A0[0], v01.x, wa); ffma2(A0[1], v01.y, wa);
                ffma2(A0[2], v23.x, wa); ffma2(A0[3], v23.y, wa);
                ffma2(B0[0], v01.x, wb); ffma2(B0[1], v01.y, wb);
                ffma2(B0[2], v23.x, wb); ffma2(B0[3], v23.y, wb);
                if (TWO){
                    float2 w1 = *(const float2*)&Wt[TWO][k][2*op];
                    ull wc = pk2(w1.x, w1.x), wd = pk2(w1.y, w1.y);
                    ffma2(A1[0], v01.x, wc); ffma2(A1[1], v01.y, wc);
                    ffma2(A1[2], v23.x, wc); ffma2(A1[3], v23.y, wc);
                    ffma2(B1[0], v01.x, wd); ffma2(B1[1], v01.y, wd);
                    ffma2(B1[2], v23.x, wd); ffma2(B1[3], v23.y, wd);
                }
            }
        }
    }

    if (!DOLN){
        __half2* o1h = (__half2*)out1;
        __half2* o2h = (__half2*)out2;
        #pragma unroll
        for (int j = 0; j < 4; j++){
            size_t r0 = rowbase + rg*8 + 2*j;
            float a0,a1,b0,b1;
            upk2(A0[j], a0, a1); upk2(B0[j], b0, b1);
            o1h[r0*32 + op]     = __float22half2_rn(make_float2(a0, b0));
            o1h[(r0+1)*32 + op] = __float22half2_rn(make_float2(a1, b1));
            if (TWO){
                upk2(A1[j], a0, a1); upk2(B1[j], b0, b1);
                o2h[r0*32 + op]     = __float22half2_rn(make_float2(a0, b0));
                o2h[(r0+1)*32 + op] = __float22half2_rn(make_float2(a1, b1));
            }
        }
    } else {
        float* o1f = (float*)out1;
        float2 bv = *(const float2*)(bias + 2*op);
        float2 wa1, wav2, wb1, wbv2;
        bool doscal = DOSCAL && (Wa2 != 0);
        if (DOSCAL && doscal){
            wa1  = *(const float2*)(Wa2 + 2*op);
            wav2 = *(const float2*)(Wa2 + 64 + 2*op);
            wb1  = *(const float2*)(Wb2 + 2*op);
            wbv2 = *(const float2*)(Wb2 + 64 + 2*op);
        }
        #pragma unroll
        for (int j = 0; j < 4; j++){
            size_t r0 = rowbase + rg*8 + 2*j;
            float a0,a1,b0,b1;
            upk2(A0[j], a0, a1); upk2(B0[j], b0, b1);
            float y00 = actf(a0 + bv.x), y01 = actf(b0 + bv.y);
            float y10 = actf(a1 + bv.x), y11 = actf(b1 + bv.y);
            if (resid){
                float2 rv0 = *(const float2*)(resid + r0*HH + 2*op);
                float2 rv1 = *(const float2*)(resid + (r0+1)*HH + 2*op);
                y00 += rv0.x; y01 += rv0.y; y10 += rv1.x; y11 += rv1.y;
            }
            float s0 = y00+y01, q0 = y00*y00+y01*y01;
            float s1 = y10+y11, q1 = y10*y10+y11*y11;
            #pragma unroll
            for (int o=16;o;o>>=1){
                s0 += __shfl_xor_sync(0xffffffffu,s0,o);
                q0 += __shfl_xor_sync(0xffffffffu,q0,o);
                s1 += __shfl_xor_sync(0xffffffffu,s1,o);
                q1 += __shfl_xor_sync(0xffffffffu,q1,o);
            }
            float m0 = s0*(1.f/64.f), m1 = s1*(1.f/64.f);
            float i0 = rsqrtf(q0*(1.f/64.f) - m0*m0 + 1e-5f);
            float i1 = rsqrtf(q1*(1.f/64.f) - m1*m1 + 1e-5f);
            float2 w0 = make_float2((y00-m0)*i0, (y01-m0)*i0);
            float2 w1 = make_float2((y10-m1)*i1, (y11-m1)*i1);
            *(float2*)(o1f + r0*HH + 2*op)     = w0;
            *(float2*)(o1f + (r0+1)*HH + 2*op) = w1;
            if (outB){
                *(float2*)(outB + r0*HH + 2*op)     = w0;
                *(float2*)(outB + (r0+1)*HH + 2*op) = w1;
            }
            if (DOSCAL && doscal){
                float pa0 = actf(w0.x)*wa1.x + actf(w0.y)*wa1.y;
                float pq0 = actf(w0.x)*wav2.x + actf(w0.y)*wav2.y;
                float pb0 = w0.x*wb1.x + w0.y*wb1.y;
                float pc0 = w0.x*wbv2.x + w0.y*wbv2.y;
                float pa1 = actf(w1.x)*wa1.x + actf(w1.y)*wa1.y;
                float pq1 = actf(w1.x)*wav2.x + actf(w1.y)*wav2.y;
                float pb1 = w1.x*wb1.x + w1.y*wb1.y;
                float pc1 = w1.x*wbv2.x + w1.y*wbv2.y;
                #pragma unroll
                for (int o=16;o;o>>=1){
                    pa0 += __shfl_xor_sync(0xffffffffu,pa0,o);
                    pq0 += __shfl_xor_sync(0xffffffffu,pq0,o);
                    pb0 += __shfl_xor_sync(0xffffffffu,pb0,o);
                    pc0 += __shfl_xor_sync(0xffffffffu,pc0,o);
                    pa1 += __shfl_xor_sync(0xffffffffu,pa1,o);
                    pq1 += __shfl_xor_sync(0xffffffffu,pq1,o);
                    pb1 += __shfl_xor_sync(0xffffffffu,pb1,o);
                    pc1 += __shfl_xor_sync(0xffffffffu,pc1,o);
                }
                if (op == 0){
                    g_Ar[r0]   = pa0 + ba2[0]; g_Aq[r0]   = pq0;
                    g_Br[r0]   = pb0 + bb2[0]; g_Bq[r0]   = pc0;
                    g_Ar[r0+1] = pa1 + ba2[0]; g_Aq[r0+1] = pq1;
                    g_Br[r0+1] = pb1 + bb2[0]; g_Bq[r0+1] = pc1;
                }
            }
        }
    }
}

// ---------------- scatter (int2-packed) | relscal L0 | zero cnt | layer-0 projections ----------------
__global__ __launch_bounds__(256, 3) void k_scatter(const int* __restrict__ col,
        const int* __restrict__ row, const int* __restrict__ et, const int* __restrict__ eq,
        const float* __restrict__ Wa0, const float* __restrict__ Wb0,
        const float* __restrict__ ba0, const float* __restrict__ bb0,
        const float* __restrict__ Wmsg0, const float* __restrict__ Wht0){
    int b = blockIdx.x;
    if (b < 1024){
        int e = b*blockDim.x + threadIdx.x;
        int c = col[e], r = row[e], t = et[e], q = eq[e];
        int p  = atomicAdd(&g_cur_n[r], 1);
        g_recN[p] = make_int2(c | (t << 16), q);
        int p2 = atomicAdd(&g_cur_t[t], 1);
        g_recT[p2] = make_int2(c | (r << 16), q);
    } else if (b < 2024){
        relscal_body(b - 1024, Wa0, Wb0, ba0, bb0);
    } else if (b < 2280){
        g_cnt_n[(b-2024)*256 + threadIdx.x] = 0;
    } else if (b < 2312){
        int i = (b-2280)*256 + threadIdx.x;
        if (i < RTT) g_cnt_t[i] = 0;
    } else if (b < 2437){
        proj_body<1,0,0>(b-2312, g_rel, 1, 0, Wmsg0, 192, 64, 128, g_prh, g_pqh, 0, 0, 0, 0,0,0,0);
    } else if (b < 2562){
        proj_body<0,0,0>(b-2437, g_rel, 1, 0, Wht0, 192, 128, 0, g_pq2h, 0, 0, 0, 0, 0,0,0,0);
    } else {
        proj_body<0,0,0>(b-2562, g_node, 1, 0, Wmsg0, 192, 0, 0, g_projAh, 0, 0, 0, 0, 0,0,0,0);
    }
}

// ---------------- attention segment sums (body) ----------------
__device__ __forceinline__ void absum_body(int b2){
    if (b2 < 256){
        int n = b2*256 + threadIdx.x;
        int b = g_off_n[n], e = g_off_n[n+1];
        float s = 0.f;
        for (int j = b; j < e; j++){
            int2 rc = g_recN[j];
            float a = __expf(g_Ar[((unsigned)rc.x) >> 16] + g_Aq[rc.y]);
            g_aes[j] = a; s += a;
        }
        g_asum[n] = s;
    } else {
        int w = (b2 - 256)*8 + (threadIdx.x >> 5);
        int lane = threadIdx.x & 31;
        if (w >= RTT) return;
        int b = g_off_t[w], e = g_off_t[w+1];
        float br = g_Br[w];
        float s = 0.f;
        for (int j = b + lane; j < e; j += 32){
            float bv = __expf(br + g_Bq[g_recT[j].y]);
            g_bes[j] = bv; s += bv;
        }
        #pragma unroll
        for (int o=16;o;o>>=1) s += __shfl_xor_sync(0xffffffffu,s,o);
        if (lane == 0) g_bsum[w] = s;
    }
}

// layer-0 absum (projections already done in scatter grid)
__global__ void k_absum0(){
    absum_body(blockIdx.x);
}

// ---------------- loop update: one warp per query ----------------
__device__ __forceinline__ void loop_warp(int q, const float* __restrict__ Wl,
                                          const float* __restrict__ bl){
    int lane = threadIdx.x & 31;
    int qrow = g_qrows[q];
    float2 lv = *(const float2*)(g_loop + q*HH + 2*lane);
    float s0 = bl[2*lane], s1 = bl[2*lane+1];
    const float* lrow = g_loop + q*HH;
    const float* rrow = g_rel + (size_t)qrow*HH;
    const float* w0p = Wl + (size_t)(2*lane)*128;
    const float* w1p = w0p + 128;
    #pragma unroll 8
    for (int k = 0; k < 64; k++){
        float c = lrow[k];
        s0 = fmaf(c, w0p[k], s0); s1 = fmaf(c, w1p[k], s1);
    }
    #pragma unroll 8
    for (int k = 0; k < 64; k++){
        float c = rrow[k];
        s0 = fmaf(c, w0p[64+k], s0); s1 = fmaf(c, w1p[64+k], s1);
    }
    float y0 = lv.x + actf(s0), y1 = lv.y + actf(s1);
    float ss = y0+y1, sq = y0*y0+y1*y1;
    #pragma unroll
    for (int o=16;o;o>>=1){
        ss += __shfl_xor_sync(0xffffffffu,ss,o);
        sq += __shfl_xor_sync(0xffffffffu,sq,o);
    }
    float m = ss*(1.f/64.f);
    float inv = rsqrtf(sq*(1.f/64.f) - m*m + 1e-5f);
    *(float2*)(g_loop + q*HH + 2*lane) = make_float2((y0-m)*inv, (y1-m)*inv);
}

// ---------------- stage kernels ----------------
// stage1 (layers >=1): Pr+Pq (dual) | Pq2 | Ph (node) | absum | loop(prev)
__global__ __launch_bounds__(256, 3) void k_stage1(const float* __restrict__ Wmsg,
        const float* __restrict__ Wht,
        const float* __restrict__ Wl_prev, const float* __restrict__ bl_prev){
    int b = blockIdx.x;
    if (b < 125)
        proj_body<1,0,0>(b, g_rel, 1, 0, Wmsg, 192, 64, 128, g_prh, g_pqh, 0, 0, 0, 0,0,0,0);
    else if (b < 250)
        proj_body<0,0,0>(b-125, g_rel, 1, 0, Wht, 192, 128, 0, g_pq2h, 0, 0, 0, 0, 0,0,0,0);
    else if (b < 1274)
        proj_body<0,0,0>(b-250, g_node, 1, 0, Wmsg, 192, 0, 0, g_projAh, 0, 0, 0, 0, 0,0,0,0);
    else if (b < 2530)
        absum_body(b-1274);
    else {
        if (threadIdx.x < 32) loop_warp(b-2530, Wl_prev, bl_prev);
    }
}

// stage4: Ph2+Pt2 (node dual)
__global__ __launch_bounds__(256, 3) void k_stage4(const float* __restrict__ Wht){
    proj_body<1,0,0>(blockIdx.x, g_node, 1, 0, Wht, 192, 0, 64, g_projAh, g_projBh, 0, 0, 0, 0,0,0,0);
}

// stage3: node = LN(act(nacc @ We^T + be))
__global__ __launch_bounds__(256, 3) void k_stage3(const float* __restrict__ We,
        const float* __restrict__ be){
    proj_body<0,1,0>(blockIdx.x, g_nacc, 1, 0, We, 64, 0, 0, g_node, 0, be, 0, 0, 0,0,0,0);
}

// stage6: rel = LN(act(racc @ Wr^T + br) + rel); finals[i]; + next-layer relscal
__global__ __launch_bounds__(256, 3) void k_stage6(const float* __restrict__ Wr,
        const float* __restrict__ br, float* __restrict__ finals_i,
        const float* __restrict__ Wa2, const float* __restrict__ Wb2,
        const float* __restrict__ ba2, const float* __restrict__ bb2){
    proj_body<0,1,1>(blockIdx.x, g_racc, 1, 0, Wr, 64, 0, 0, g_rel, 0, br, g_rel, finals_i,
                     Wa2, Wb2, ba2, bb2);
}

// final: fin = LN(act(concat(finals) @ Wf^T + bf)) | loop(layer 2)
__global__ __launch_bounds__(256, 3) void k_final(const float* __restrict__ Wf,
        const float* __restrict__ bf, const float* __restrict__ Wl2,
        const float* __restrict__ bl2){
    int b = blockIdx.x;
    if (b < 125)
        proj_body<0,1,0>(b, g_finals, 3, (size_t)RTT*HH, Wf, 192, 0, 0, g_fin, 0, bf, 0, 0, 0,0,0,0);
    else {
        if (threadIdx.x < 32) loop_warp(b-125, Wl2, bl2);
    }
}

// ---------------- edge message aggregation: half-warp per edge stream (2-way) ----------------
__global__ void k_msg_agg(const int* __restrict__ row, const float* __restrict__ bmsg){
    int w = (blockIdx.x*blockDim.x + threadIdx.x) >> 5;
    int lane = threadIdx.x & 31;
    if (w >= NN) return;
    int half = lane >> 4, hl = lane & 15;     // dims 4hl..4hl+3
    int b = g_off_n[w], e = g_off_n[w+1];
    float denom = g_asum[row[w]] + 1e-10f;    // faithful a_sum[row[row_e]]
    float sc0 = g_dinv2[w] / denom;
    float4 bm = *(const float4*)(bmsg + 4*hl);
    const __half2* phA = (const __half2*)g_projAh;
    const __half2* phR = (const __half2*)g_prh;
    const __half2* phQ = (const __half2*)g_pqh;
    float4 acc = make_float4(0.f,0.f,0.f,0.f);
    for (int j = b + half; j < e; j += 2){
        int2 rc = g_recN[j];
        int cl = rc.x & 0xFFFF;
        int tt = ((unsigned)rc.x) >> 16;
        float coef = g_aes[j] * sc0 * g_dinv2[cl];
        float2 pa0 = __half22float2(phA[(size_t)cl*32 + 2*hl]);
        float2 pa1 = __half22float2(phA[(size_t)cl*32 + 2*hl + 1]);
        float2 pr0 = __half22float2(phR[(size_t)tt*32 + 2*hl]);
        float2 pr1 = __half22float2(phR[(size_t)tt*32 + 2*hl + 1]);
        float2 pq0 = __half22float2(phQ[(size_t)rc.y*32 + 2*hl]);
        float2 pq1 = __half22float2(phQ[(size_t)rc.y*32 + 2*hl + 1]);
        acc.x += coef*actf(pa0.x + pr0.x + pq0.x + bm.x);
        acc.y += coef*actf(pa0.y + pr0.y + pq0.y + bm.y);
        acc.z += coef*actf(pa1.x + pr1.x + pq1.x + bm.z);
        acc.w += coef*actf(pa1.y + pr1.y + pq1.y + bm.w);
    }
    acc.x += __shfl_down_sync(0xffffffffu, acc.x, 16);
    acc.y += __shfl_down_sync(0xffffffffu, acc.y, 16);
    acc.z += __shfl_down_sync(0xffffffffu, acc.z, 16);
    acc.w += __shfl_down_sync(0xffffffffu, acc.w, 16);
    if (half == 0) *(float4*)(g_nacc + (size_t)w*HH + 4*hl) = acc;
}

// ---------------- ht2r aggregation: quarter-warp per edge stream (4-way) ----------------
__global__ void k_ht2r_agg(const int* __restrict__ et, const float* __restrict__ bht){
    int w = (blockIdx.x*blockDim.x + threadIdx.x) >> 5;
    int lane = threadIdx.x & 31;
    if (w >= RTT) return;
    int qd = lane >> 3, ql = lane & 7;   // dims 8ql..8ql+7
    int b = g_off_t[w], e = g_off_t[w+1];
    float inv_denom = 1.f / (g_bsum[et[w]] + 1e-10f);  // faithful b_sum[et[et_e]]
    float4 bm0 = *(const float4*)(bht + 8*ql);
    float4 bm1 = *(const float4*)(bht + 8*ql + 4);
    const __half2* phA = (const __half2*)g_projAh;
    const __half2* phB = (const __half2*)g_projBh;
    const __half2* phQ = (const __half2*)g_pq2h;
    float acc[8];
    #pragma unroll
    for (int x=0;x<8;x++) acc[x] = 0.f;
    for (int j = b + qd; j < e; j += 4){
        int2 rc = g_recT[j];
        int cl = rc.x & 0xFFFF;
        unsigned rw = ((unsigned)rc.x) >> 16;
        float coef = g_bes[j] * inv_denom;
        float2 pa[4], pt[4], pq[4];
        #pragma unroll
        for (int x=0;x<4;x++){
            pa[x] = __half22float2(phA[(size_t)cl*32 + 4*ql + x]);
            pt[x] = __half22float2(phB[(size_t)rw*32 + 4*ql + x]);
            pq[x] = __half22float2(phQ[(size_t)rc.y*32 + 4*ql + x]);
        }
        acc[0] += coef*actf(pa[0].x + pt[0].x + pq[0].x + bm0.x);
        acc[1] += coef*actf(pa[0].y + pt[0].y + pq[0].y + bm0.y);
        acc[2] += coef*actf(pa[1].x + pt[1].x + pq[1].x + bm0.z);
        acc[3] += coef*actf(pa[1].y + pt[1].y + pq[1].y + bm0.w);
        acc[4] += coef*actf(pa[2].x + pt[2].x + pq[2].x + bm1.x);
        acc[5] += coef*actf(pa[2].y + pt[2].y + pq[2].y + bm1.y);
        acc[6] += coef*actf(pa[3].x + pt[3].x + pq[3].x + bm1.z);
        acc[7] += coef*actf(pa[3].y + pt[3].y + pq[3].y + bm1.w);
    }
    #pragma unroll
    for (int x=0;x<8;x++){
        acc[x] += __shfl_down_sync(0xffffffffu, acc[x], 16);
        acc[x] += __shfl_down_sync(0xffffffffu, acc[x], 8);
    }
    if (qd == 0){
        *(float4*)(g_racc + (size_t)w*HH + 8*ql)     = make_float4(acc[0],acc[1],acc[2],acc[3]);
        *(float4*)(g_racc + (size_t)w*HH + 8*ql + 4) = make_float4(acc[4],acc[5],acc[6],acc[7]);
    }
}

// ---------------- output means | zero rel for next call ----------------
__global__ void k_mean(float* __restrict__ out){
    int b = blockIdx.x;
    if (b < 402){
        int idx = b*256 + threadIdx.x;
        if (idx >= 8*201*64) return;
        int h = idx & 63;
        int rb = idx >> 6;
        int r = rb % 201;
        int bq = rb / 201;
        float s = 0.f;
        if (r < 200){
            #pragma unroll
            for (int s5=0;s5<5;s5++) s += g_fin[(bq*1000 + s5*200 + r)*HH + h];
        } else {
            #pragma unroll
            for (int s5=0;s5<5;s5++) s += g_loop[(bq*5 + s5)*HH + h];
        }
        out[idx] = s * 0.2f;
    } else {
        g_rel[(b-402)*256 + threadIdx.x] = 0.f;   // RTT*HH = 512000 = 2000 blocks
    }
}

// ---------------- host ----------------
struct Ptrs {
    const int *ei,*et,*eq,*hp,*tp,*qr,*lab;
    const float *pos,*srel,*lemb,*Wmsg,*bmsg,*Wht,*bht,*Wa,*ba,*Wb,*bb,*Wl,*bl,*We,*be,*Wr,*br,*Wf,*bf;
};

static void resolve(void* const* d, const int* sz, int n, Ptrs& p){
    int gi, wi;
    if (sz[0] == 2*EN){
        gi = 0;
        wi = (n > 10 && sz[7] == 1 && sz[8] == 1 && sz[9] == 1) ? 10 : 7;
    } else {
        wi = 0; gi = 19;
    }
    p.ei  = (const int*)d[gi+0]; p.et = (const int*)d[gi+1]; p.eq = (const int*)d[gi+2];
    p.hp  = (const int*)d[gi+3]; p.tp = (const int*)d[gi+4]; p.qr = (const int*)d[gi+5];
    p.lab = (const int*)d[gi+6];
    p.pos  = (const float*)d[wi+0];  p.srel = (const float*)d[wi+1];  p.lemb = (const float*)d[wi+2];
    p.Wmsg = (const float*)d[wi+3];  p.bmsg = (const float*)d[wi+4];
    p.Wht  = (const float*)d[wi+5];  p.bht  = (const float*)d[wi+6];
    p.Wa   = (const float*)d[wi+7];  p.ba   = (const float*)d[wi+8];
    p.Wb   = (const float*)d[wi+9];  p.bb   = (const float*)d[wi+10];
    p.Wl   = (const float*)d[wi+11]; p.bl   = (const float*)d[wi+12];
    p.We   = (const float*)d[wi+13]; p.be   = (const float*)d[wi+14];
    p.Wr   = (const float*)d[wi+15]; p.br   = (const float*)d[wi+16];
    p.Wf   = (const float*)d[wi+17]; p.bf   = (const float*)d[wi+18];
}

extern "C" void kernel_launch(void* const* d_in, const int* in_sizes, int n_in,
                              void* d_out, int out_size){
    Ptrs p; resolve(d_in, in_sizes, n_in, p);
    const int* col = p.ei;
    const int* row = p.ei + EN;

    float* s_finals;
    cudaGetSymbolAddress((void**)&s_finals, g_finals);

    // ---- init + CSR build (cnt/rel pre-zeroed by prior call's tails / module load) ----
    k_inithist<<<INIT_NODE_BLK + INIT_REL_BLK + INIT_HIST_BLK, 256>>>(
        p.lab, p.pos, p.hp, p.tp, p.qr, p.srel, p.lemb, row, p.et);
    k_scan1<<<72,1024>>>();
    k_scan3<<<72,1024>>>();
    // scatter + layer-0 relscal + cnt zero + layer-0 projections
    k_scatter<<<3586,256>>>(col, row, p.et, p.eq, p.Wa, p.Wb, p.ba, p.bb,
                            p.Wmsg, p.Wht);

    for (int i = 0; i < 3; i++){
        const float* Wmsg = p.Wmsg + i*HH*192;
        const float* bmsg = p.bmsg + i*HH;
        const float* Wht  = p.Wht  + i*HH*192;
        const float* bht  = p.bht  + i*HH;
        const float* Wa2 = (i < 2) ? (p.Wa + (i+1)*128) : (const float*)0;
        const float* Wb2 = (i < 2) ? (p.Wb + (i+1)*128) : (const float*)0;
        const float* ba2 = (i < 2) ? (p.ba + (i+1)) : (const float*)0;
        const float* bb2 = (i < 2) ? (p.bb + (i+1)) : (const float*)0;

        if (i == 0){
            k_absum0<<<1256,256>>>();
        } else {
            k_stage1<<<2570,256>>>(Wmsg, Wht, p.Wl + (i-1)*HH*128, p.bl + (i-1)*HH);
        }
        k_msg_agg<<<NN*32/256,256>>>(row, bmsg);
        k_stage3<<<1024,256>>>(p.We + i*HH*HH, p.be + i*HH);
        k_stage4<<<1024,256>>>(Wht);
        k_ht2r_agg<<<RTT*32/256,256>>>(p.et, bht);
        k_stage6<<<125,256>>>(p.Wr + i*HH*HH, p.br + i*HH, s_finals + i*RTT*HH,
                              Wa2, Wb2, ba2, bb2);
    }

    k_final<<<165,256>>>(p.Wf, p.bf, p.Wl + 2*HH*128, p.bl + 2*HH);
    k_mean<<<2402,256>>>((float*)d_out);
}

// round 12
// speedup vs baseline: 1.0435x; 1.0427x over previous
#include <cuda_runtime.h>
#include <cuda_fp16.h>
#include <math.h>

#define EN   262144
#define NN   65536
#define RTT  8000
#define HH   64
#define BQn  40
#define RRn  200
#define SLOPE 0.22916666666666666f

typedef unsigned long long ull;

// ---------------- device scratch (no allocs allowed) ----------------
__device__ float  g_node[NN*HH], g_nacc[NN*HH];
__device__ __half g_projAh[NN*HH], g_projBh[NN*HH];
__device__ __half g_prh[RTT*HH], g_pqh[RTT*HH], g_pq2h[RTT*HH];
__device__ float  g_rel[RTT*HH], g_racc[RTT*HH];
__device__ float  g_finals[3*RTT*HH], g_fin[RTT*HH];
__device__ float  g_Ar[RTT], g_Aq[RTT], g_Br[RTT], g_Bq[RTT];
__device__ float  g_asum[NN], g_bsum[RTT], g_dinv2[NN];
__device__ float  g_aes[EN], g_bes[EN];
__device__ float  g_loop[BQn*HH];
__device__ int    g_qrows[BQn];
__device__ int    g_posrow[NN];
__device__ int    g_cnt_n[NN], g_off_n[NN+1], g_cur_n[NN];
__device__ int    g_cnt_t[RTT], g_off_t[RTT+1], g_cur_t[RTT];
__device__ int    g_aux[128];
__device__ int2   g_recN[EN];   // (col | et<<16, eq) grouped by row
__device__ int2   g_recT[EN];   // (col | row<<16, eq) grouped by edge_type

__device__ __forceinline__ float actf(float x){ return x >= 0.f ? x : x*SLOPE; }

__device__ __forceinline__ ull pk2(float x, float y){
    ull r; asm("mov.b64 %0, {%1, %2};" : "=l"(r) : "f"(x), "f"(y)); return r;
}
__device__ __forceinline__ void upk2(ull v, float& x, float& y){
    asm("mov.b64 {%0, %1}, %2;" : "=f"(x), "=f"(y) : "l"(v));
}
__device__ __forceinline__ void ffma2(ull& d, ull a, ull b){
    asm("fma.rn.f32x2 %0, %1, %2, %0;" : "+l"(d) : "l"(a), "l"(b));
}

// ---------------- init + hist (posrow only; no 16MB node write) ----------------
#define INIT_POS_BLK  (NN/256)             // 256
#define INIT_REL_BLK  (BQn*HH/256)         // 10
#define INIT_HIST_BLK (EN/256)             // 1024
__global__ void k_inithist(const int* __restrict__ labels,
                           const int* __restrict__ qrel, const float* __restrict__ srel,
                           const float* __restrict__ lemb,
                           const int* __restrict__ row, const int* __restrict__ et){
    int t = threadIdx.x;
    int b = blockIdx.x;
    if (b < INIT_POS_BLK){
        int n = b*256 + t;
        g_posrow[n] = labels[2*n]*4 + labels[2*n+1];
    } else if (b < INIT_POS_BLK + INIT_REL_BLK){
        int idx = (b - INIT_POS_BLK)*256 + t;
        int q = idx >> 6, h = idx & 63;
        int qrow = qrel[q] + q*RRn;
        if (h == 0) g_qrows[q] = qrow;
        g_rel[qrow*HH + h] = srel[h];   // rest of g_rel zeroed by prior call's k_mean tail
        g_loop[idx] = lemb[h];
    } else {
        int e = (b - INIT_POS_BLK - INIT_REL_BLK)*256 + t;
        atomicAdd(&g_cnt_n[row[e]], 1);
        atomicAdd(&g_cnt_t[et[e]], 1);
    }
}

// ---------------- CSR scans ----------------
__device__ __forceinline__ void scan1_body(const int* cnt, int* off, int* aux, int n, int blk){
    __shared__ int sh[1024];
    int t = threadIdx.x, i = blk*1024 + t;
    int v = (i < n) ? cnt[i] : 0;
    sh[t] = v; __syncthreads();
    for (int d = 1; d < 1024; d <<= 1){
        int u = (t >= d) ? sh[t-d] : 0;
        __syncthreads();
        sh[t] += u;
        __syncthreads();
    }
    if (i < n) off[i] = sh[t] - v;
    if (t == 1023) aux[blk] = sh[t];
}

// 73rd block: h/t posrow overrides (h first, then t wins — matches reference order)
__global__ void k_scan1(const int* __restrict__ hp, const int* __restrict__ tp){
    if (blockIdx.x < 64) scan1_body(g_cnt_n, g_off_n, g_aux, NN, blockIdx.x);
    else if (blockIdx.x < 72) scan1_body(g_cnt_t, g_off_t, g_aux + 64, RTT, blockIdx.x - 64);
    else {
        int t = threadIdx.x;
        if (t < BQn) g_posrow[hp[t]] = 0;
        __syncthreads();
        if (t < BQn) g_posrow[tp[t]] = 1;
    }
}

// scan3 computes its own aux prefix in-block (scan2 eliminated)
__device__ __forceinline__ int aux_prefix(const int* aux, int upto){
    __shared__ int sa[64];
    int t = threadIdx.x;
    if (t < 64) sa[t] = (t < upto) ? aux[t] : 0;
    __syncthreads();
    if (t < 32) sa[t] += sa[t+32];
    __syncthreads();
    int base = 0;
    if (t < 32){
        int v = sa[t];
        #pragma unroll
        for (int o=16;o;o>>=1) v += __shfl_down_sync(0xffffffffu, v, o);
        if (t == 0) sa[0] = v;
    }
    __syncthreads();
    base = sa[0];
    __syncthreads();
    return base;
}

__global__ void k_scan3(){
    int t = threadIdx.x;
    if (blockIdx.x < 64){
        int blk = blockIdx.x;
        int base = aux_prefix(g_aux, blk);
        int i = blk*1024 + t;
        int o = g_off_n[i] + base;
        g_off_n[i] = o; g_cur_n[i] = o;
        int c = g_cnt_n[i];
        g_dinv2[i] = c > 0 ? 1.f/(float)c : 0.f;
        if (i == 0) g_off_n[NN] = EN;
    } else {
        int b2 = blockIdx.x - 64;
        int base = aux_prefix(g_aux + 64, b2);
        int i = b2*1024 + t;
        if (i < RTT){
            int o = g_off_t[i] + base;
            g_off_t[i] = o; g_cur_t[i] = o;
        }
        if (i == 0) g_off_t[RTT] = EN;
    }
}

// ---------------- per-relation attention scalars (layer 0) ----------------
__device__ __forceinline__ void relscal_body(int b2, const float* __restrict__ Wa,
        const float* __restrict__ Wb, const float* __restrict__ ba, const float* __restrict__ bb){
    int w = b2*8 + (threadIdx.x >> 5);
    int lane = threadIdx.x & 31;
    if (w >= RTT) return;
    float2 v = *(const float2*)(g_rel + (size_t)w*HH + 2*lane);
    float a0 = actf(v.x), a1 = actf(v.y);
    float2 wa1 = *(const float2*)(Wa + 2*lane);
    float2 wa2 = *(const float2*)(Wa + 64 + 2*lane);
    float2 wb1 = *(const float2*)(Wb + 2*lane);
    float2 wb2 = *(const float2*)(Wb + 64 + 2*lane);
    float sar = a0*wa1.x + a1*wa1.y;
    float saq = a0*wa2.x + a1*wa2.y;
    float sbr = v.x*wb1.x + v.y*wb1.y;
    float sbq = v.x*wb2.x + v.y*wb2.y;
    #pragma unroll
    for (int o=16;o;o>>=1){
        sar += __shfl_xor_sync(0xffffffffu,sar,o);
        saq += __shfl_xor_sync(0xffffffffu,saq,o);
        sbr += __shfl_xor_sync(0xffffffffu,sbr,o);
        sbq += __shfl_xor_sync(0xffffffffu,sbq,o);
    }
    if (lane == 0){ g_Ar[w]=sar+ba[0]; g_Aq[w]=saq; g_Br[w]=sbr+bb[0]; g_Bq[w]=sbq; }
}

// ---------------- core proj body (optional row-remap gather on input) ----------------
template<int TWO, int DOLN, int DOSCAL>
__device__ __forceinline__ void proj_body(
        int blk, const float* __restrict__ in, const int* __restrict__ rmap,
        int nchunk, size_t cstride,
        const float* __restrict__ W, int wstride, int co1, int co2,
        void* __restrict__ out1, void* __restrict__ out2,
        const float* __restrict__ bias, const float* __restrict__ resid,
        float* __restrict__ outB,
        const float* __restrict__ Wa2, const float* __restrict__ Wb2,
        const float* __restrict__ ba2, const float* __restrict__ bb2)
{
    __shared__ float In[64][68];
    __shared__ float Wt[TWO+1][32][66];
    __shared__ int Rw[64];
    const int t = threadIdx.x;
    const int op = t & 31, rg = t >> 5;
    const size_t rowbase = (size_t)blk * 64;

    if (rmap && t < 64) Rw[t] = rmap[rowbase + t];

    ull A0[4], B0[4], A1[4], B1[4];
    {
        ull z = pk2(0.f, 0.f);
        #pragma unroll
        for (int j=0;j<4;j++){ A0[j]=z; B0[j]=z; A1[j]=z; B1[j]=z; }
    }

    for (int c = 0; c < nchunk; c++){
        #pragma unroll 1
        for (int h = 0; h < 2; h++){
            __syncthreads();
            if (h == 0){
                const float* inc = in + (size_t)c*cstride;
                for (int idx = t; idx < 1024; idx += 256){
                    int r = idx & 63, kq = idx >> 6;
                    size_t roff = rmap ? (size_t)Rw[r]*HH : (rowbase + r)*HH;
                    float4 v = *(const float4*)(inc + roff + 4*kq);
                    In[4*kq+0][r]=v.x; In[4*kq+1][r]=v.y;
                    In[4*kq+2][r]=v.z; In[4*kq+3][r]=v.w;
                }
            }
            {
                int cob = c*64 + h*32;
                for (int idx = t; idx < 2048; idx += 256){
                    int o = idx >> 5, k = idx & 31;
                    Wt[0][k][o] = W[o*wstride + co1 + cob + k];
                    if (TWO) Wt[TWO][k][o] = W[o*wstride + co2 + cob + k];
                }
            }
            __syncthreads();
            #pragma unroll 8
            for (int k = 0; k < 32; k++){
                ulonglong2 v01 = *(const ulonglong2*)&In[h*32+k][rg*8];
                ulonglong2 v23 = *(const ulonglong2*)&In[h*32+k][rg*8+4];
                float2 w0 = *(const float2*)&Wt[0][k][2*op];
                ull wa = pk2(w0.x, w0.x), wb = pk2(w0.y, w0.y);
                ffma2(A0[0], v01.x, wa); ffma2(A0[1], v01.y, wa);
                ffma2(A0[2], v23.x, wa); ffma2(A0[3], v23.y, wa);
                ffma2(B0[0], v01.x, wb); ffma2(B0[1], v01.y, wb);
                ffma2(B0[2], v23.x, wb); ffma2(B0[3], v23.y, wb);
                if (TWO){
                    float2 w1 = *(const float2*)&Wt[TWO][k][2*op];
                    ull wc = pk2(w1.x, w1.x), wd = pk2(w1.y, w1.y);
                    ffma2(A1[0], v01.x, wc); ffma2(A1[1], v01.y, wc);
                    ffma2(A1[2], v23.x, wc); ffma2(A1[3], v23.y, wc);
                    ffma2(B1[0], v01.x, wd); ffma2(B1[1], v01.y, wd);
                    ffma2(B1[2], v23.x, wd); ffma2(B1[3], v23.y, wd);
                }
            }
        }
    }

    if (!DOLN){
        __half2* o1h = (__half2*)out1;
        __half2* o2h = (__half2*)out2;
        #pragma unroll
        for (int j = 0; j < 4; j++){
            size_t r0 = rowbase + rg*8 + 2*j;
            float a0,a1,b0,b1;
            upk2(A0[j], a0, a1); upk2(B0[j], b0, b1);
            o1h[r0*32 + op]     = __float22half2_rn(make_float2(a0, b0));
            o1h[(r0+1)*32 + op] = __float22half2_rn(make_float2(a1, b1));
            if (TWO){
                upk2(A1[j], a0, a1); upk2(B1[j], b0, b1);
                o2h[r0*32 + op]     = __float22half2_rn(make_float2(a0, b0));
                o2h[(r0+1)*32 + op] = __float22half2_rn(make_float2(a1, b1));
            }
        }
    } else {
        float* o1f = (float*)out1;
        float2 bv = *(const float2*)(bias + 2*op);
        float2 wa1, wav2, wb1, wbv2;
        bool doscal = DOSCAL && (Wa2 != 0);
        if (DOSCAL && doscal){
            wa1  = *(const float2*)(Wa2 + 2*op);
            wav2 = *(const float2*)(Wa2 + 64 + 2*op);
            wb1  = *(const float2*)(Wb2 + 2*op);
            wbv2 = *(const float2*)(Wb2 + 64 + 2*op);
        }
        #pragma unroll
        for (int j = 0; j < 4; j++){
            size_t r0 = rowbase + rg*8 + 2*j;
            float a0,a1,b0,b1;
            upk2(A0[j], a0, a1); upk2(B0[j], b0, b1);
            float y00 = actf(a0 + bv.x), y01 = actf(b0 + bv.y);
            float y10 = actf(a1 + bv.x), y11 = actf(b1 + bv.y);
            if (resid){
                float2 rv0 = *(const float2*)(resid + r0*HH + 2*op);
                float2 rv1 = *(const float2*)(resid + (r0+1)*HH + 2*op);
                y00 += rv0.x; y01 += rv0.y; y10 += rv1.x; y11 += rv1.y;
            }
            float s0 = y00+y01, q0 = y00*y00+y01*y01;
            float s1 = y10+y11, q1 = y10*y10+y11*y11;
            #pragma unroll
            for (int o=16;o;o>>=1){
                s0 += __shfl_xor_sync(0xffffffffu,s0,o);
                q0 += __shfl_xor_sync(0xffffffffu,q0,o);
                s1 += __shfl_xor_sync(0xffffffffu,s1,o);
                q1 += __shfl_xor_sync(0xffffffffu,q1,o);
            }
            float m0 = s0*(1.f/64.f), m1 = s1*(1.f/64.f);
            float i0 = rsqrtf(q0*(1.f/64.f) - m0*m0 + 1e-5f);
            float i1 = rsqrtf(q1*(1.f/64.f) - m1*m1 + 1e-5f);
            float2 w0 = make_float2((y00-m0)*i0, (y01-m0)*i0);
            float2 w1 = make_float2((y10-m1)*i1, (y11-m1)*i1);
            *(float2*)(o1f + r0*HH + 2*op)     = w0;
            *(float2*)(o1f + (r0+1)*HH + 2*op) = w1;
            if (outB){
                *(float2*)(outB + r0*HH + 2*op)     = w0;
                *(float2*)(outB + (r0+1)*HH + 2*op) = w1;
            }
            if (DOSCAL && doscal){
                float pa0 = actf(w0.x)*wa1.x + actf(w0.y)*wa1.y;
                float pq0 = actf(w0.x)*wav2.x + actf(w0.y)*wav2.y;
                float pb0 = w0.x*wb1.x + w0.y*wb1.y;
                float pc0 = w0.x*wbv2.x + w0.y*wbv2.y;
                float pa1 = actf(w1.x)*wa1.x + actf(w1.y)*wa1.y;
                float pq1 = actf(w1.x)*wav2.x + actf(w1.y)*wav2.y;
                float pb1 = w1.x*wb1.x + w1.y*wb1.y;
                float pc1 = w1.x*wbv2.x + w1.y*wbv2.y;
                #pragma unroll
                for (int o=16;o;o>>=1){
                    pa0 += __shfl_xor_sync(0xffffffffu,pa0,o);
                    pq0 += __shfl_xor_sync(0xffffffffu,pq0,o);
                    pb0 += __shfl_xor_sync(0xffffffffu,pb0,o);
                    pc0 += __shfl_xor_sync(0xffffffffu,pc0,o);
                    pa1 += __shfl_xor_sync(0xffffffffu,pa1,o);
                    pq1 += __shfl_xor_sync(0xffffffffu,pq1,o);
                    pb1 += __shfl_xor_sync(0xffffffffu,pb1,o);
                    pc1 += __shfl_xor_sync(0xffffffffu,pc1,o);
                }
                if (op == 0){
                    g_Ar[r0]   = pa0 + ba2[0]; g_Aq[r0]   = pq0;
                    g_Br[r0]   = pb0 + bb2[0]; g_Bq[r0]   = pc0;
                    g_Ar[r0+1] = pa1 + ba2[0]; g_Aq[r0+1] = pq1;
                    g_Br[r0+1] = pb1 + bb2[0]; g_Bq[r0+1] = pc1;
                }
            }
        }
    }
}

// ---------------- scatter | relscal L0 | zero cnt | layer-0 projections (Ph via pos_emb gather) ----------------
__global__ __launch_bounds__(256, 3) void k_scatter(const int* __restrict__ col,
        const int* __restrict__ row, const int* __restrict__ et, const int* __restrict__ eq,
        const float* __restrict__ Wa0, const float* __restrict__ Wb0,
        const float* __restrict__ ba0, const float* __restrict__ bb0,
        const float* __restrict__ Wmsg0, const float* __restrict__ Wht0,
        const float* __restrict__ pos_emb){
    int b = blockIdx.x;
    if (b < 1024){
        int e = b*blockDim.x + threadIdx.x;
        int c = col[e], r = row[e], t = et[e], q = eq[e];
        int p  = atomicAdd(&g_cur_n[r], 1);
        g_recN[p] = make_int2(c | (t << 16), q);
        int p2 = atomicAdd(&g_cur_t[t], 1);
        g_recT[p2] = make_int2(c | (r << 16), q);
    } else if (b < 2024){
        relscal_body(b - 1024, Wa0, Wb0, ba0, bb0);
    } else if (b < 2280){
        g_cnt_n[(b-2024)*256 + threadIdx.x] = 0;
    } else if (b < 2312){
        int i = (b-2280)*256 + threadIdx.x;
        if (i < RTT) g_cnt_t[i] = 0;
    } else if (b < 2437){
        proj_body<1,0,0>(b-2312, g_rel, 0, 1, 0, Wmsg0, 192, 64, 128, g_prh, g_pqh, 0, 0, 0, 0,0,0,0);
    } else if (b < 2562){
        proj_body<0,0,0>(b-2437, g_rel, 0, 1, 0, Wht0, 192, 128, 0, g_pq2h, 0, 0, 0, 0, 0,0,0,0);
    } else {
        // layer-0 Ph: gather rows from 4KB pos_emb via posrow (no 16MB node table)
        proj_body<0,0,0>(b-2562, pos_emb, g_posrow, 1, 0, Wmsg0, 192, 0, 0, g_projAh, 0, 0, 0, 0, 0,0,0,0);
    }
}

// ---------------- attention segment sums (body) ----------------
__device__ __forceinline__ void absum_body(int b2){
    if (b2 < 256){
        int n = b2*256 + threadIdx.x;
        int b = g_off_n[n], e = g_off_n[n+1];
        float s = 0.f;
        for (int j = b; j < e; j++){
            int2 rc = g_recN[j];
            float a = __expf(g_Ar[((unsigned)rc.x) >> 16] + g_Aq[rc.y]);
            g_aes[j] = a; s += a;
        }
        g_asum[n] = s;
    } else {
        int w = (b2 - 256)*8 + (threadIdx.x >> 5);
        int lane = threadIdx.x & 31;
        if (w >= RTT) return;
        int b = g_off_t[w], e = g_off_t[w+1];
        float br = g_Br[w];
        float s = 0.f;
        for (int j = b + lane; j < e; j += 32){
            float bv = __expf(br + g_Bq[g_recT[j].y]);
            g_bes[j] = bv; s += bv;
        }
        #pragma unroll
        for (int o=16;o;o>>=1) s += __shfl_xor_sync(0xffffffffu,s,o);
        if (lane == 0) g_bsum[w] = s;
    }
}

// layer-0 absum (projections already done in scatter grid)
__global__ void k_absum0(){
    absum_body(blockIdx.x);
}

// ---------------- loop update: one warp per query ----------------
__device__ __forceinline__ void loop_warp(int q, const float* __restrict__ Wl,
                                          const float* __restrict__ bl){
    int lane = threadIdx.x & 31;
    int qrow = g_qrows[q];
    float2 lv = *(const float2*)(g_loop + q*HH + 2*lane);
    float s0 = bl[2*lane], s1 = bl[2*lane+1];
    const float* lrow = g_loop + q*HH;
    const float* rrow = g_rel + (size_t)qrow*HH;
    const float* w0p = Wl + (size_t)(2*lane)*128;
    const float* w1p = w0p + 128;
    #pragma unroll 8
    for (int k = 0; k < 64; k++){
        float c = lrow[k];
        s0 = fmaf(c, w0p[k], s0); s1 = fmaf(c, w1p[k], s1);
    }
    #pragma unroll 8
    for (int k = 0; k < 64; k++){
        float c = rrow[k];
        s0 = fmaf(c, w0p[64+k], s0); s1 = fmaf(c, w1p[64+k], s1);
    }
    float y0 = lv.x + actf(s0), y1 = lv.y + actf(s1);
    float ss = y0+y1, sq = y0*y0+y1*y1;
    #pragma unroll
    for (int o=16;o;o>>=1){
        ss += __shfl_xor_sync(0xffffffffu,ss,o);
        sq += __shfl_xor_sync(0xffffffffu,sq,o);
    }
    float m = ss*(1.f/64.f);
    float inv = rsqrtf(sq*(1.f/64.f) - m*m + 1e-5f);
    *(float2*)(g_loop + q*HH + 2*lane) = make_float2((y0-m)*inv, (y1-m)*inv);
}

// ---------------- stage kernels ----------------
// stage1 (layers >=1): Pr+Pq (dual) | Pq2 | Ph (node) | absum | loop(prev)
__global__ __launch_bounds__(256, 3) void k_stage1(const float* __restrict__ Wmsg,
        const float* __restrict__ Wht,
        const float* __restrict__ Wl_prev, const float* __restrict__ bl_prev){
    int b = blockIdx.x;
    if (b < 125)
        proj_body<1,0,0>(b, g_rel, 0, 1, 0, Wmsg, 192, 64, 128, g_prh, g_pqh, 0, 0, 0, 0,0,0,0);
    else if (b < 250)
        proj_body<0,0,0>(b-125, g_rel, 0, 1, 0, Wht, 192, 128, 0, g_pq2h, 0, 0, 0, 0, 0,0,0,0);
    else if (b < 1274)
        proj_body<0,0,0>(b-250, g_node, 0, 1, 0, Wmsg, 192, 0, 0, g_projAh, 0, 0, 0, 0, 0,0,0,0);
    else if (b < 2530)
        absum_body(b-1274);
    else {
        if (threadIdx.x < 32) loop_warp(b-2530, Wl_prev, bl_prev);
    }
}

// stage4: Ph2+Pt2 (node dual)
__global__ __launch_bounds__(256, 3) void k_stage4(const float* __restrict__ Wht){
    proj_body<1,0,0>(blockIdx.x, g_node, 0, 1, 0, Wht, 192, 0, 64, g_projAh, g_projBh, 0, 0, 0, 0,0,0,0);
}

// stage3: node = LN(act(nacc @ We^T + be))
__global__ __launch_bounds__(256, 3) void k_stage3(const float* __restrict__ We,
        const float* __restrict__ be){
    proj_body<0,1,0>(blockIdx.x, g_nacc, 0, 1, 0, We, 64, 0, 0, g_node, 0, be, 0, 0, 0,0,0,0);
}

// stage6: rel = LN(act(racc @ Wr^T + br) + rel); finals[i]; + next-layer relscal
__global__ __launch_bounds__(256, 3) void k_stage6(const float* __restrict__ Wr,
        const float* __restrict__ br, float* __restrict__ finals_i,
        const float* __restrict__ Wa2, const float* __restrict__ Wb2,
        const float* __restrict__ ba2, const float* __restrict__ bb2){
    proj_body<0,1,1>(blockIdx.x, g_racc, 0, 1, 0, Wr, 64, 0, 0, g_rel, 0, br, g_rel, finals_i,
                     Wa2, Wb2, ba2, bb2);
}

// final: fin = LN(act(concat(finals) @ Wf^T + bf)) | loop(layer 2)
__global__ __launch_bounds__(256, 3) void k_final(const float* __restrict__ Wf,
        const float* __restrict__ bf, const float* __restrict__ Wl2,
        const float* __restrict__ bl2){
    int b = blockIdx.x;
    if (b < 125)
        proj_body<0,1,0>(b, g_finals, 0, 3, (size_t)RTT*HH, Wf, 192, 0, 0, g_fin, 0, bf, 0, 0, 0,0,0,0);
    else {
        if (threadIdx.x < 32) loop_warp(b-125, Wl2, bl2);
    }
}

// ---------------- edge message aggregation: warp per node (r8 layout) ----------------
__global__ void k_msg_agg(const int* __restrict__ row, const float* __restrict__ bmsg){
    int w = (blockIdx.x*blockDim.x + threadIdx.x) >> 5;
    int lane = threadIdx.x & 31;
    if (w >= NN) return;
    int b = g_off_n[w], e = g_off_n[w+1];
    float denom = g_asum[row[w]] + 1e-10f;    // faithful a_sum[row[row_e]]
    float sc0 = g_dinv2[w] / denom;
    float2 bm = *(const float2*)(bmsg + 2*lane);
    const __half2* phA = (const __half2*)g_projAh;
    const __half2* phR = (const __half2*)g_prh;
    const __half2* phQ = (const __half2*)g_pqh;
    float ax = 0.f, ay = 0.f;
    for (int j = b; j < e; j++){
        int2 rc = g_recN[j];
        int cl = rc.x & 0xFFFF;
        int tt = ((unsigned)rc.x) >> 16;
        float coef = g_aes[j] * sc0 * g_dinv2[cl];
        float2 ph = __half22float2(phA[(size_t)cl*32 + lane]);
        float2 pr = __half22float2(phR[(size_t)tt*32 + lane]);
        float2 pq = __half22float2(phQ[(size_t)rc.y*32 + lane]);
        ax += coef*actf(ph.x + pr.x + pq.x + bm.x);
        ay += coef*actf(ph.y + pr.y + pq.y + bm.y);
    }
    *(float2*)(g_nacc + (size_t)w*HH + 2*lane) = make_float2(ax, ay);
}

// ---------------- ht2r aggregation: warp per relation type (r8 layout) ----------------
__global__ void k_ht2r_agg(const int* __restrict__ et, const float* __restrict__ bht){
    int w = (blockIdx.x*blockDim.x + threadIdx.x) >> 5;
    int lane = threadIdx.x & 31;
    if (w >= RTT) return;
    int b = g_off_t[w], e = g_off_t[w+1];
    float inv_denom = 1.f / (g_bsum[et[w]] + 1e-10f);  // faithful b_sum[et[et_e]]
    float2 bm = *(const float2*)(bht + 2*lane);
    const __half2* phA = (const __half2*)g_projAh;
    const __half2* phB = (const __half2*)g_projBh;
    const __half2* phQ = (const __half2*)g_pq2h;
    float ax = 0.f, ay = 0.f;
    for (int j = b; j < e; j++){
        int2 rc = g_recT[j];
        int cl = rc.x & 0xFFFF;
        unsigned rw = ((unsigned)rc.x) >> 16;
        float coef = g_bes[j] * inv_denom;
        float2 ph = __half22float2(phA[(size_t)cl*32 + lane]);
        float2 pt = __half22float2(phB[(size_t)rw*32 + lane]);
        float2 pq = __half22float2(phQ[(size_t)rc.y*32 + lane]);
        ax += coef*actf(ph.x + pt.x + pq.x + bm.x);
        ay += coef*actf(ph.y + pt.y + pq.y + bm.y);
    }
    *(float2*)(g_racc + (size_t)w*HH + 2*lane) = make_float2(ax, ay);
}

// ---------------- output means | zero rel for next call ----------------
__global__ void k_mean(float* __restrict__ out){
    int b = blockIdx.x;
    if (b < 402){
        int idx = b*256 + threadIdx.x;
        if (idx >= 8*201*64) return;
        int h = idx & 63;
        int rb = idx >> 6;
        int r = rb % 201;
        int bq = rb / 201;
        float s = 0.f;
        if (r < 200){
            #pragma unroll
            for (int s5=0;s5<5;s5++) s += g_fin[(bq*1000 + s5*200 + r)*HH + h];
        } else {
            #pragma unroll
            for (int s5=0;s5<5;s5++) s += g_loop[(bq*5 + s5)*HH + h];
        }
        out[idx] = s * 0.2f;
    } else {
        g_rel[(b-402)*256 + threadIdx.x] = 0.f;   // RTT*HH = 512000 = 2000 blocks
    }
}

// ---------------- host ----------------
struct Ptrs {
    const int *ei,*et,*eq,*hp,*tp,*qr,*lab;
    const float *pos,*srel,*lemb,*Wmsg,*bmsg,*Wht,*bht,*Wa,*ba,*Wb,*bb,*Wl,*bl,*We,*be,*Wr,*br,*Wf,*bf;
};

static void resolve(void* const* d, const int* sz, int n, Ptrs& p){
    int gi, wi;
    if (sz[0] == 2*EN){
        gi = 0;
        wi = (n > 10 && sz[7] == 1 && sz[8] == 1 && sz[9] == 1) ? 10 : 7;
    } else {
        wi = 0; gi = 19;
    }
    p.ei  = (const int*)d[gi+0]; p.et = (const int*)d[gi+1]; p.eq = (const int*)d[gi+2];
    p.hp  = (const int*)d[gi+3]; p.tp = (const int*)d[gi+4]; p.qr = (const int*)d[gi+5];
    p.lab = (const int*)d[gi+6];
    p.pos  = (const float*)d[wi+0];  p.srel = (const float*)d[wi+1];  p.lemb = (const float*)d[wi+2];
    p.Wmsg = (const float*)d[wi+3];  p.bmsg = (const float*)d[wi+4];
    p.Wht  = (const float*)d[wi+5];  p.bht  = (const float*)d[wi+6];
    p.Wa   = (const float*)d[wi+7];  p.ba   = (const float*)d[wi+8];
    p.Wb   = (const float*)d[wi+9];  p.bb   = (const float*)d[wi+10];
    p.Wl   = (const float*)d[wi+11]; p.bl   = (const float*)d[wi+12];
    p.We   = (const float*)d[wi+13]; p.be   = (const float*)d[wi+14];
    p.Wr   = (const float*)d[wi+15]; p.br   = (const float*)d[wi+16];
    p.Wf   = (const float*)d[wi+17]; p.bf   = (const float*)d[wi+18];
}

extern "C" void kernel_launch(void* const* d_in, const int* in_sizes, int n_in,
                              void* d_out, int out_size){
    Ptrs p; resolve(d_in, in_sizes, n_in, p);
    const int* col = p.ei;
    const int* row = p.ei + EN;

    float* s_finals;
    cudaGetSymbolAddress((void**)&s_finals, g_finals);

    // ---- init + CSR build (cnt/rel pre-zeroed by prior call's tails / module load) ----
    k_inithist<<<INIT_POS_BLK + INIT_REL_BLK + INIT_HIST_BLK, 256>>>(
        p.lab, p.qr, p.srel, p.lemb, row, p.et);
    k_scan1<<<73,1024>>>(p.hp, p.tp);
    k_scan3<<<72,1024>>>();
    // scatter + layer-0 relscal + cnt zero + layer-0 projections (Ph gathers pos_emb)
    k_scatter<<<3586,256>>>(col, row, p.et, p.eq, p.Wa, p.Wb, p.ba, p.bb,
                            p.Wmsg, p.Wht, p.pos);

    for (int i = 0; i < 3; i++){
        const float* Wmsg = p.Wmsg + i*HH*192;
        const float* bmsg = p.bmsg + i*HH;
        const float* Wht  = p.Wht  + i*HH*192;
        const float* bht  = p.bht  + i*HH;
        const float* Wa2 = (i < 2) ? (p.Wa + (i+1)*128) : (const float*)0;
        const float* Wb2 = (i < 2) ? (p.Wb + (i+1)*128) : (const float*)0;
        const float* ba2 = (i < 2) ? (p.ba + (i+1)) : (const float*)0;
        const float* bb2 = (i < 2) ? (p.bb + (i+1)) : (const float*)0;

        if (i == 0){
            k_absum0<<<1256,256>>>();
        } else {
            k_stage1<<<2570,256>>>(Wmsg, Wht, p.Wl + (i-1)*HH*128, p.bl + (i-1)*HH);
        }
        k_msg_agg<<<NN*32/256,256>>>(row, bmsg);
        k_stage3<<<1024,256>>>(p.We + i*HH*HH, p.be + i*HH);
        k_stage4<<<1024,256>>>(Wht);
        k_ht2r_agg<<<RTT*32/256,256>>>(p.et, bht);
        k_stage6<<<125,256>>>(p.Wr + i*HH*HH, p.br + i*HH, s_finals + i*RTT*HH,
                              Wa2, Wb2, ba2, bb2);
    }

    k_final<<<165,256>>>(p.Wf, p.bf, p.Wl + 2*HH*128, p.bl + 2*HH);
    k_mean<<<2402,256>>>((float*)d_out);
}